// round 4
// baseline (speedup 1.0000x reference)
#include <cuda_runtime.h>
#include <cuda_bf16.h>
#include <cstdint>
#include <math.h>

#define S_SAMP 32
#define BATCH  1024
#define D_IN   784
#define D_H    1024
#define D_OUT  10
#define K0PAD  832            // 784 padded to multiple of 32

// ---------------------------------------------------------------------------
// Device scratch (static: no cudaMalloc allowed)
// ---------------------------------------------------------------------------
__device__ __nv_bfloat16 g_xhi[(size_t)BATCH * K0PAD];
__device__ __nv_bfloat16 g_xlo[(size_t)BATCH * K0PAD];
__device__ __nv_bfloat16 g_w0hi[(size_t)S_SAMP * D_H * K0PAD];   // [S][N][Kpad] transposed
__device__ __nv_bfloat16 g_w0lo[(size_t)S_SAMP * D_H * K0PAD];
__device__ __nv_bfloat16 g_w1hi[(size_t)S_SAMP * D_H * D_H];
__device__ __nv_bfloat16 g_w1lo[(size_t)S_SAMP * D_H * D_H];
__device__ __nv_bfloat16 g_a0hi[(size_t)S_SAMP * BATCH * D_H];
__device__ __nv_bfloat16 g_a0lo[(size_t)S_SAMP * BATCH * D_H];
__device__ float         g_act1[(size_t)S_SAMP * BATCH * D_H];
__device__ float g_b0[S_SAMP * D_H];
__device__ float g_b1[S_SAMP * D_H];
__device__ float g_wl[S_SAMP * D_H * D_OUT];
__device__ float g_bl[S_SAMP * D_OUT];

// ---------------------------------------------------------------------------
// PTX helpers (arch-neutral only: cp.async, ldmatrix, mma.sync)
// ---------------------------------------------------------------------------
__device__ __forceinline__ uint32_t smem_u32(const void* p) {
    uint32_t a;
    asm("{ .reg .u64 t; cvta.to.shared.u64 t, %1; cvt.u32.u64 %0, t; }" : "=r"(a) : "l"(p));
    return a;
}
__device__ __forceinline__ void cp16(uint32_t dst, const void* src) {
    asm volatile("cp.async.cg.shared.global [%0], [%1], 16;" :: "r"(dst), "l"(src) : "memory");
}
#define CP_COMMIT() asm volatile("cp.async.commit_group;" ::: "memory")
#define CP_WAIT(n)  asm volatile("cp.async.wait_group %0;" :: "n"(n) : "memory")

__device__ __forceinline__ void ldsm4(uint32_t* r, uint32_t addr) {
    asm volatile("ldmatrix.sync.aligned.m8n8.x4.shared.b16 {%0,%1,%2,%3}, [%4];"
        : "=r"(r[0]), "=r"(r[1]), "=r"(r[2]), "=r"(r[3]) : "r"(addr));
}
__device__ __forceinline__ void mma_bf16(float* d, const uint32_t* a, const uint32_t* b) {
    asm volatile("mma.sync.aligned.m16n8k16.row.col.f32.bf16.bf16.f32 "
        "{%0,%1,%2,%3}, {%4,%5,%6,%7}, {%8,%9}, {%0,%1,%2,%3};"
        : "+f"(d[0]), "+f"(d[1]), "+f"(d[2]), "+f"(d[3])
        : "r"(a[0]), "r"(a[1]), "r"(a[2]), "r"(a[3]), "r"(b[0]), "r"(b[1]));
}

// ---------------------------------------------------------------------------
// Prep kernels
// ---------------------------------------------------------------------------
__global__ void prep_x(const float* __restrict__ x,
                       __nv_bfloat16* __restrict__ xhi, __nv_bfloat16* __restrict__ xlo) {
    int i = blockIdx.x * blockDim.x + threadIdx.x;
    if (i >= BATCH * K0PAD) return;
    int b = i / K0PAD, k = i - b * K0PAD;
    float v = (k < D_IN) ? x[b * D_IN + k] : 0.0f;
    __nv_bfloat16 h = __float2bfloat16(v);
    xhi[i] = h;
    xlo[i] = __float2bfloat16(v - __bfloat162float(h));
}

// Sample + transpose weights: out[s][n][kpad] = we[s][k][n]*exp(.5 wv[k][n]) + wm[k][n]
__global__ void prep_wt(const float* __restrict__ we, const float* __restrict__ wv,
                        const float* __restrict__ wm,
                        __nv_bfloat16* __restrict__ whi, __nv_bfloat16* __restrict__ wlo,
                        int K, int N, int Kpad) {
    __shared__ float t[32][33];
    int s = blockIdx.z;
    int k0 = blockIdx.x * 32, n0 = blockIdx.y * 32;
    int tx = threadIdx.x, ty = threadIdx.y;       // 32 x 8
#pragma unroll
    for (int i = 0; i < 4; i++) {
        int k = k0 + ty + i * 8;
        float val = 0.0f;
        if (k < K) {
            size_t idx = (size_t)k * N + n0 + tx;
            val = fmaf(we[(size_t)s * K * N + idx], expf(0.5f * wv[idx]), wm[idx]);
        }
        t[ty + i * 8][tx] = val;
    }
    __syncthreads();
#pragma unroll
    for (int i = 0; i < 4; i++) {
        int n = n0 + ty + i * 8;
        float v = t[tx][ty + i * 8];
        __nv_bfloat16 h = __float2bfloat16(v);
        size_t off = ((size_t)s * N + n) * Kpad + k0 + tx;
        whi[off] = h;
        wlo[off] = __float2bfloat16(v - __bfloat162float(h));
    }
}

__global__ void prep_sample(const float* __restrict__ e, const float* __restrict__ v,
                            const float* __restrict__ m, float* __restrict__ out,
                            int n, int total) {
    int i = blockIdx.x * blockDim.x + threadIdx.x;
    if (i < total) {
        int j = i % n;
        out[i] = fmaf(e[i], expf(0.5f * v[j]), m[j]);
    }
}

// ---------------------------------------------------------------------------
// HMMA GEMM with fused bf16 hi/lo split (3-term):
//   C[s] = relu(A[s] @ W[s]^T + bias[s])
//   Term order ah*bh, al*bh, then reload B buffer with blo -> ah*blo.
//   Peak live regs: 64 acc + 8 ah + 8 al + 16 b = 96 + addressing (<128).
// ---------------------------------------------------------------------------
#define GBM 128
#define GBN 128
#define GBK 32
#define ROWB 80                      // padded smem row stride (bytes)
#define MATB (128 * ROWB)            // 10240 B per matrix tile
#define STAGEB (4 * MATB)            // Ahi,Alo,Bhi,Blo = 40960 B
#define SMEM_TOTAL (2 * STAGEB)      // 81920 B

__global__ void __launch_bounds__(256, 2) gemm_mma(
    const __nv_bfloat16* __restrict__ Ahi, const __nv_bfloat16* __restrict__ Alo,
    size_t aStrideS, int Kpad,
    const __nv_bfloat16* __restrict__ Whi, const __nv_bfloat16* __restrict__ Wlo,
    const float* __restrict__ bias,
    float* __restrict__ Cf,
    __nv_bfloat16* __restrict__ Chi, __nv_bfloat16* __restrict__ Clo,
    int mode)
{
    extern __shared__ __align__(16) char dynsmem[];
    const uint32_t sbase = smem_u32(dynsmem);

    const int tid  = threadIdx.x;
    const int wid  = tid >> 5;
    const int lane = tid & 31;
    const int s  = blockIdx.z;
    const int m0 = blockIdx.y * GBM;
    const int n0 = blockIdx.x * GBN;

    const int warp_m = wid >> 1;          // 0..3 -> 32-row strip
    const int warp_n = wid & 1;           // 0..1 -> 64-col strip

    const __nv_bfloat16* aHiG = Ahi + (size_t)s * aStrideS + (size_t)m0 * Kpad;
    const __nv_bfloat16* aLoG = Alo + (size_t)s * aStrideS + (size_t)m0 * Kpad;
    const __nv_bfloat16* wHiG = Whi + ((size_t)s * D_H + n0) * Kpad;
    const __nv_bfloat16* wLoG = Wlo + ((size_t)s * D_H + n0) * Kpad;

    // loader: 256 threads -> (row 0..127, sel hi/lo), 4 x 16B chunks per row
    const int lrow = tid & 127;
    const int lsel = tid >> 7;            // 0 = hi, 1 = lo
    const __nv_bfloat16* aSrc = (lsel ? aLoG : aHiG) + (size_t)lrow * Kpad;
    const __nv_bfloat16* bSrc = (lsel ? wLoG : wHiG) + (size_t)lrow * Kpad;
    const uint32_t aDstRow = lsel * MATB + lrow * ROWB;            // Ahi/Alo
    const uint32_t bDstRow = (2 + lsel) * MATB + lrow * ROWB;      // Bhi/Blo

    // ldmatrix per-lane offsets
    const uint32_t aLaneOff = (uint32_t)(lane & 15) * ROWB + (uint32_t)(lane >> 4) * 16;
    const uint32_t bLaneOff = (uint32_t)((lane & 7) + ((lane & 16) >> 1)) * ROWB
                            + (uint32_t)((lane >> 3) & 1) * 16;
    const uint32_t aWarpOff = (uint32_t)(warp_m * 32) * ROWB;
    const uint32_t bWarpOff = (uint32_t)(warp_n * 64) * ROWB;

    float acc[2][8][4];
#pragma unroll
    for (int i = 0; i < 2; i++)
#pragma unroll
        for (int j = 0; j < 8; j++)
#pragma unroll
            for (int q = 0; q < 4; q++) acc[i][j][q] = 0.0f;

    const int nchunks = Kpad / GBK;

    // prologue: load chunk 0 into stage 0
    {
#pragma unroll
        for (int c = 0; c < 4; c++) {
            cp16(sbase + aDstRow + c * 16, aSrc + c * 8);
            cp16(sbase + bDstRow + c * 16, bSrc + c * 8);
        }
        CP_COMMIT();
    }

    for (int it = 0; it < nchunks; it++) {
        // prefetch next chunk
        if (it + 1 < nchunks) {
            const uint32_t st = sbase + ((it + 1) & 1) * STAGEB;
            const int k0 = (it + 1) * GBK;
#pragma unroll
            for (int c = 0; c < 4; c++) {
                cp16(st + aDstRow + c * 16, aSrc + k0 + c * 8);
                cp16(st + bDstRow + c * 16, bSrc + k0 + c * 8);
            }
            CP_COMMIT();
            CP_WAIT(1);
        } else {
            CP_WAIT(0);
        }
        __syncthreads();

        const uint32_t st  = sbase + (it & 1) * STAGEB;
        const uint32_t aHiS = st + aWarpOff + aLaneOff;
        const uint32_t aLoS = st + MATB + aWarpOff + aLaneOff;
        const uint32_t bHiS = st + 2 * MATB + bWarpOff + bLaneOff;
        const uint32_t bLoS = st + 3 * MATB + bWarpOff + bLaneOff;

#pragma unroll
        for (int ks = 0; ks < 2; ks++) {
            const uint32_t ko = ks * 32;  // 16 bf16 = 32 B per k16 step
            uint32_t ah[2][4], al[2][4], bb[16];
#pragma unroll
            for (int mi = 0; mi < 2; mi++)
                ldsm4(ah[mi], aHiS + mi * 16 * ROWB + ko);
#pragma unroll
            for (int mi = 0; mi < 2; mi++)
                ldsm4(al[mi], aLoS + mi * 16 * ROWB + ko);
#pragma unroll
            for (int p = 0; p < 4; p++)
                ldsm4(&bb[p * 4], bHiS + p * 16 * ROWB + ko);
            // term 1: hi * hi
#pragma unroll
            for (int mi = 0; mi < 2; mi++)
#pragma unroll
                for (int nj = 0; nj < 8; nj++)
                    mma_bf16(acc[mi][nj], ah[mi], &bb[nj * 2]);
            // term 2: lo * hi (B buffer still holds bh)
#pragma unroll
            for (int mi = 0; mi < 2; mi++)
#pragma unroll
                for (int nj = 0; nj < 8; nj++)
                    mma_bf16(acc[mi][nj], al[mi], &bb[nj * 2]);
            // reload B buffer with blo, term 3: hi * lo
#pragma unroll
            for (int p = 0; p < 4; p++)
                ldsm4(&bb[p * 4], bLoS + p * 16 * ROWB + ko);
#pragma unroll
            for (int mi = 0; mi < 2; mi++)
#pragma unroll
                for (int nj = 0; nj < 8; nj++)
                    mma_bf16(acc[mi][nj], ah[mi], &bb[nj * 2]);
        }
        __syncthreads();
    }

    // ---- epilogue ----
    const int colBase = n0 + warp_n * 64 + (lane & 3) * 2;
    const int rowBase = m0 + warp_m * 32 + (lane >> 2);
    float bias2[8][2];
#pragma unroll
    for (int nj = 0; nj < 8; nj++) {
        const float* bp = bias + (size_t)s * D_H + colBase + nj * 8;
        bias2[nj][0] = bp[0];
        bias2[nj][1] = bp[1];
    }

#pragma unroll
    for (int mi = 0; mi < 2; mi++) {
#pragma unroll
        for (int h = 0; h < 2; h++) {
            const int row = rowBase + mi * 16 + h * 8;
            const size_t rowOff = ((size_t)s * BATCH + row) * D_H;
#pragma unroll
            for (int nj = 0; nj < 8; nj++) {
                float v0 = fmaxf(acc[mi][nj][2 * h]     + bias2[nj][0], 0.0f);
                float v1 = fmaxf(acc[mi][nj][2 * h + 1] + bias2[nj][1], 0.0f);
                const int n = colBase + nj * 8;
                if (mode == 0) {
                    __nv_bfloat16 h0 = __float2bfloat16(v0);
                    __nv_bfloat16 h1 = __float2bfloat16(v1);
                    __nv_bfloat16 l0 = __float2bfloat16(v0 - __bfloat162float(h0));
                    __nv_bfloat16 l1 = __float2bfloat16(v1 - __bfloat162float(h1));
                    *(uint32_t*)((uint16_t*)Chi + rowOff + n) =
                        (uint32_t)__bfloat16_as_ushort(h0) | ((uint32_t)__bfloat16_as_ushort(h1) << 16);
                    *(uint32_t*)((uint16_t*)Clo + rowOff + n) =
                        (uint32_t)__bfloat16_as_ushort(l0) | ((uint32_t)__bfloat16_as_ushort(l1) << 16);
                } else {
                    *(float2*)(Cf + rowOff + n) = make_float2(v0, v1);
                }
            }
        }
    }
}

// ---------------------------------------------------------------------------
// Last layer (fp32): out[s,b,o] = act[s,b,:] . wl[s,:,o] + bl[s,o]
// ---------------------------------------------------------------------------
__global__ void __launch_bounds__(256) layer_out(
    const float* __restrict__ act, const float* __restrict__ wls,
    const float* __restrict__ bls, float* __restrict__ out)
{
    const int s  = blockIdx.y;
    const int m0 = blockIdx.x * 128;

    __shared__ float As[128][33];
    __shared__ float ws[32 * D_OUT];

    const int tid   = threadIdx.x;
    const int crow  = tid >> 1;
    const int obase = (tid & 1) * 5;

    float acc[5] = {0.f, 0.f, 0.f, 0.f, 0.f};
    const int lr = tid >> 3;
    const int lk = (tid & 7) * 4;

    for (int kt = 0; kt < D_H; kt += 32) {
#pragma unroll
        for (int rr = 0; rr < 4; rr++) {
            int r = lr + rr * 32;
            float4 v = *(const float4*)(act + ((size_t)s * BATCH + m0 + r) * D_H + kt + lk);
            As[r][lk + 0] = v.x; As[r][lk + 1] = v.y; As[r][lk + 2] = v.z; As[r][lk + 3] = v.w;
        }
        for (int i = tid; i < 32 * D_OUT; i += 256)
            ws[i] = wls[(size_t)s * D_H * D_OUT + kt * D_OUT + i];
        __syncthreads();
#pragma unroll
        for (int k = 0; k < 32; k++) {
            float a = As[crow][k];
#pragma unroll
            for (int j = 0; j < 5; j++)
                acc[j] = fmaf(a, ws[k * D_OUT + obase + j], acc[j]);
        }
        __syncthreads();
    }
#pragma unroll
    for (int j = 0; j < 5; j++)
        out[((size_t)s * BATCH + m0 + crow) * D_OUT + obase + j] = acc[j] + bls[s * D_OUT + obase + j];
}

// ---------------------------------------------------------------------------
// kernel_launch
//   Launch order chosen so launch index 5 (ncu -s 5 -c 1) is gemm_mma L0.
// ---------------------------------------------------------------------------
extern "C" void kernel_launch(void* const* d_in, const int* in_sizes, int n_in,
                              void* d_out, int out_size) {
    const float* x   = (const float*)d_in[0];
    const float* wm0 = (const float*)d_in[1];
    const float* wv0 = (const float*)d_in[2];
    const float* bm0 = (const float*)d_in[3];
    const float* bv0 = (const float*)d_in[4];
    const float* wm1 = (const float*)d_in[5];
    const float* wv1 = (const float*)d_in[6];
    const float* bm1 = (const float*)d_in[7];
    const float* bv1 = (const float*)d_in[8];
    const float* wlm = (const float*)d_in[9];
    const float* wlv = (const float*)d_in[10];
    const float* blm = (const float*)d_in[11];
    const float* blv = (const float*)d_in[12];
    const float* we0 = (const float*)d_in[13];
    const float* be0 = (const float*)d_in[14];
    const float* we1 = (const float*)d_in[15];
    const float* be1 = (const float*)d_in[16];
    const float* wel = (const float*)d_in[17];
    const float* bel = (const float*)d_in[18];
    float* out = (float*)d_out;

    __nv_bfloat16 *xhi, *xlo, *w0hi, *w0lo, *w1hi, *w1lo, *a0hi, *a0lo;
    float *act1, *b0, *b1, *wl, *bl;
    cudaGetSymbolAddress((void**)&xhi,  g_xhi);
    cudaGetSymbolAddress((void**)&xlo,  g_xlo);
    cudaGetSymbolAddress((void**)&w0hi, g_w0hi);
    cudaGetSymbolAddress((void**)&w0lo, g_w0lo);
    cudaGetSymbolAddress((void**)&w1hi, g_w1hi);
    cudaGetSymbolAddress((void**)&w1lo, g_w1lo);
    cudaGetSymbolAddress((void**)&a0hi, g_a0hi);
    cudaGetSymbolAddress((void**)&a0lo, g_a0lo);
    cudaGetSymbolAddress((void**)&act1, g_act1);
    cudaGetSymbolAddress((void**)&b0,   g_b0);
    cudaGetSymbolAddress((void**)&b1,   g_b1);
    cudaGetSymbolAddress((void**)&wl,   g_wl);
    cudaGetSymbolAddress((void**)&bl,   g_bl);

    static bool attr_set = false;
    if (!attr_set) {
        cudaFuncSetAttribute(gemm_mma, cudaFuncAttributeMaxDynamicSharedMemorySize, SMEM_TOTAL);
        attr_set = true;
    }

    // launches 0..4: preps needed by the GEMMs
    {
        int n = BATCH * K0PAD;
        prep_x<<<(n + 255) / 256, 256>>>(x, xhi, xlo);                       // 0
    }
    {
        dim3 blk(32, 8);
        dim3 g0(K0PAD / 32, D_H / 32, S_SAMP);
        prep_wt<<<g0, blk>>>(we0, wv0, wm0, w0hi, w0lo, D_IN, D_H, K0PAD);   // 1
        dim3 g1(D_H / 32, D_H / 32, S_SAMP);
        prep_wt<<<g1, blk>>>(we1, wv1, wm1, w1hi, w1lo, D_H, D_H, D_H);      // 2
    }
    {
        int total = S_SAMP * D_H;
        prep_sample<<<(total + 255) / 256, 256>>>(be0, bv0, bm0, b0, D_H, total); // 3
        prep_sample<<<(total + 255) / 256, 256>>>(be1, bv1, bm1, b1, D_H, total); // 4
    }

    // launch 5: layer 0 GEMM (profiled by ncu -s 5 -c 1)
    {
        dim3 grid(D_H / GBN, BATCH / GBM, S_SAMP);
        gemm_mma<<<grid, 256, SMEM_TOTAL>>>(xhi, xlo, 0, K0PAD,
                                            w0hi, w0lo, b0,
                                            nullptr, a0hi, a0lo, 0);
    }
    // launch 6: layer 1 GEMM
    {
        dim3 grid(D_H / GBN, BATCH / GBM, S_SAMP);
        gemm_mma<<<grid, 256, SMEM_TOTAL>>>(a0hi, a0lo, (size_t)BATCH * D_H, D_H,
                                            w1hi, w1lo, b1,
                                            act1, nullptr, nullptr, 1);
    }
    // launches 7..8: last-layer sampling preps (only needed before layer_out)
    {
        int total = S_SAMP * D_H * D_OUT;
        prep_sample<<<(total + 255) / 256, 256>>>(wel, wlv, wlm, wl, D_H * D_OUT, total);
        total = S_SAMP * D_OUT;
        prep_sample<<<(total + 255) / 256, 256>>>(bel, blv, blm, bl, D_OUT, total);
    }
    // launch 9: final layer
    {
        dim3 grid(BATCH / 128, S_SAMP);
        layer_out<<<grid, 256>>>(act1, wl, bl, out);
    }
}

// round 5
// speedup vs baseline: 1.3591x; 1.3591x over previous
#include <cuda_runtime.h>
#include <cuda_fp16.h>
#include <cstdint>
#include <math.h>

#define S_SAMP 32
#define BATCH  1024
#define D_IN   784
#define D_H    1024
#define D_OUT  10
#define K0PAD  832            // 784 padded to multiple of 32

// ---------------------------------------------------------------------------
// Device scratch (static: no cudaMalloc allowed)
// ---------------------------------------------------------------------------
__device__ __half g_x16[(size_t)BATCH * K0PAD];
__device__ __half g_w0hi[(size_t)S_SAMP * D_H * K0PAD];   // [S][N][Kpad] transposed
__device__ __half g_w0lo[(size_t)S_SAMP * D_H * K0PAD];
__device__ __half g_w1hi[(size_t)S_SAMP * D_H * D_H];
__device__ __half g_w1lo[(size_t)S_SAMP * D_H * D_H];
__device__ __half g_a016[(size_t)S_SAMP * BATCH * D_H];
__device__ float  g_act1[(size_t)S_SAMP * BATCH * D_H];
__device__ float g_b0[S_SAMP * D_H];
__device__ float g_b1[S_SAMP * D_H];
__device__ float g_wl[S_SAMP * D_H * D_OUT];
__device__ float g_bl[S_SAMP * D_OUT];

// ---------------------------------------------------------------------------
// PTX helpers (arch-neutral only: cp.async, ldmatrix, mma.sync)
// ---------------------------------------------------------------------------
__device__ __forceinline__ uint32_t smem_u32(const void* p) {
    uint32_t a;
    asm("{ .reg .u64 t; cvta.to.shared.u64 t, %1; cvt.u32.u64 %0, t; }" : "=r"(a) : "l"(p));
    return a;
}
__device__ __forceinline__ void cp16(uint32_t dst, const void* src) {
    asm volatile("cp.async.cg.shared.global [%0], [%1], 16;" :: "r"(dst), "l"(src) : "memory");
}
#define CP_COMMIT() asm volatile("cp.async.commit_group;" ::: "memory")
#define CP_WAIT(n)  asm volatile("cp.async.wait_group %0;" :: "n"(n) : "memory")

__device__ __forceinline__ void ldsm4(uint32_t* r, uint32_t addr) {
    asm volatile("ldmatrix.sync.aligned.m8n8.x4.shared.b16 {%0,%1,%2,%3}, [%4];"
        : "=r"(r[0]), "=r"(r[1]), "=r"(r[2]), "=r"(r[3]) : "r"(addr));
}
__device__ __forceinline__ void mma_f16(float* d, const uint32_t* a, const uint32_t* b) {
    asm volatile("mma.sync.aligned.m16n8k16.row.col.f32.f16.f16.f32 "
        "{%0,%1,%2,%3}, {%4,%5,%6,%7}, {%8,%9}, {%0,%1,%2,%3};"
        : "+f"(d[0]), "+f"(d[1]), "+f"(d[2]), "+f"(d[3])
        : "r"(a[0]), "r"(a[1]), "r"(a[2]), "r"(a[3]), "r"(b[0]), "r"(b[1]));
}

// ---------------------------------------------------------------------------
// Prep kernels
// ---------------------------------------------------------------------------
__global__ void prep_x(const float* __restrict__ x, __half* __restrict__ x16) {
    int i = blockIdx.x * blockDim.x + threadIdx.x;
    if (i >= BATCH * K0PAD) return;
    int b = i / K0PAD, k = i - b * K0PAD;
    float v = (k < D_IN) ? x[b * D_IN + k] : 0.0f;
    x16[i] = __float2half(v);
}

// Sample + transpose weights: W[s][n][kpad] = we[s][k][n]*exp(.5 wv[k][n]) + wm[k][n]
// stored as fp16 hi + fp16 residual lo
__global__ void prep_wt(const float* __restrict__ we, const float* __restrict__ wv,
                        const float* __restrict__ wm,
                        __half* __restrict__ whi, __half* __restrict__ wlo,
                        int K, int N, int Kpad) {
    __shared__ float t[32][33];
    int s = blockIdx.z;
    int k0 = blockIdx.x * 32, n0 = blockIdx.y * 32;
    int tx = threadIdx.x, ty = threadIdx.y;       // 32 x 8
#pragma unroll
    for (int i = 0; i < 4; i++) {
        int k = k0 + ty + i * 8;
        float val = 0.0f;
        if (k < K) {
            size_t idx = (size_t)k * N + n0 + tx;
            val = fmaf(we[(size_t)s * K * N + idx], expf(0.5f * wv[idx]), wm[idx]);
        }
        t[ty + i * 8][tx] = val;
    }
    __syncthreads();
#pragma unroll
    for (int i = 0; i < 4; i++) {
        int n = n0 + ty + i * 8;
        float v = t[tx][ty + i * 8];
        __half h = __float2half(v);
        size_t off = ((size_t)s * N + n) * Kpad + k0 + tx;
        whi[off] = h;
        wlo[off] = __float2half(v - __half2float(h));
    }
}

__global__ void prep_sample(const float* __restrict__ e, const float* __restrict__ v,
                            const float* __restrict__ m, float* __restrict__ out,
                            int n, int total) {
    int i = blockIdx.x * blockDim.x + threadIdx.x;
    if (i < total) {
        int j = i % n;
        out[i] = fmaf(e[i], expf(0.5f * v[j]), m[j]);
    }
}

// ---------------------------------------------------------------------------
// HMMA GEMM, fp16 2-term: C[s] = relu(A16[s] @ (Wh+Wl)[s]^T + bias[s])
//   A: single fp16 [.][M][Kpad]; W: fp16 hi/lo [S][N][Kpad] (K-major rows).
//   CTA tile 128x128x32, 8 warps (warp tile 32x64), double-buffered cp.async.
//   Smem rows padded to 80B (coprime 8 -> LDSM conflict-free).
//   mode 0: write fp16 (feeds next GEMM); mode 1: write fp32.
// ---------------------------------------------------------------------------
#define GBM 128
#define GBN 128
#define GBK 32
#define ROWB 80                      // padded smem row stride (bytes)
#define MATB (128 * ROWB)            // 10240 B per matrix tile
#define STAGEB (3 * MATB)            // A, Wh, Wl = 30720 B
#define SMEM_TOTAL (2 * STAGEB)      // 61440 B

__global__ void __launch_bounds__(256, 2) gemm_mma(
    const __half* __restrict__ A16, size_t aStrideS, int Kpad,
    const __half* __restrict__ Whi, const __half* __restrict__ Wlo,
    const float* __restrict__ bias,
    float* __restrict__ Cf, __half* __restrict__ Ch,
    int mode)
{
    extern __shared__ __align__(16) char dynsmem[];
    const uint32_t sbase = smem_u32(dynsmem);

    const int tid  = threadIdx.x;
    const int wid  = tid >> 5;
    const int lane = tid & 31;
    const int s  = blockIdx.z;
    const int m0 = blockIdx.y * GBM;
    const int n0 = blockIdx.x * GBN;

    const int warp_m = wid >> 1;          // 0..3 -> 32-row strip
    const int warp_n = wid & 1;           // 0..1 -> 64-col strip

    const __half* aG   = A16 + (size_t)s * aStrideS + (size_t)m0 * Kpad;
    const __half* wHiG = Whi + ((size_t)s * D_H + n0) * Kpad;
    const __half* wLoG = Wlo + ((size_t)s * D_H + n0) * Kpad;

    // Loader assignment per chunk (1536 cp16 over 256 threads = 6 each):
    //   tid 0..127  : A row tid, 4 chunks
    //   tid 128..255: Wh row tid-128, 4 chunks
    //   all tid     : Wl row tid>>1, 2 chunks at (tid&1)*2
    const int lrowA  = tid & 127;
    const int firstHalf = (tid < 128);
    const __half* src4 = firstHalf ? (aG + (size_t)lrowA * Kpad)
                                   : (wHiG + (size_t)lrowA * Kpad);
    const uint32_t dst4Row = (firstHalf ? 0 : MATB) + (uint32_t)lrowA * ROWB;
    const int lrowL = tid >> 1;
    const __half* srcL = wLoG + (size_t)lrowL * Kpad;
    const uint32_t dstLRow = 2 * MATB + (uint32_t)lrowL * ROWB;
    const int cL = (tid & 1) * 2;

    // ldmatrix per-lane offsets
    const uint32_t aLaneOff = (uint32_t)(lane & 15) * ROWB + (uint32_t)(lane >> 4) * 16;
    const uint32_t bLaneOff = (uint32_t)((lane & 7) + ((lane & 16) >> 1)) * ROWB
                            + (uint32_t)((lane >> 3) & 1) * 16;
    const uint32_t aWarpOff = (uint32_t)(warp_m * 32) * ROWB;
    const uint32_t bWarpOff = (uint32_t)(warp_n * 64) * ROWB;

    float acc[2][8][4];
#pragma unroll
    for (int i = 0; i < 2; i++)
#pragma unroll
        for (int j = 0; j < 8; j++)
#pragma unroll
            for (int q = 0; q < 4; q++) acc[i][j][q] = 0.0f;

    const int nchunks = Kpad / GBK;

    // prologue: load chunk 0 into stage 0
    {
#pragma unroll
        for (int c = 0; c < 4; c++)
            cp16(sbase + dst4Row + c * 16, src4 + c * 8);
#pragma unroll
        for (int j = 0; j < 2; j++)
            cp16(sbase + dstLRow + (cL + j) * 16, srcL + (cL + j) * 8);
        CP_COMMIT();
    }

    for (int it = 0; it < nchunks; it++) {
        // prefetch next chunk
        if (it + 1 < nchunks) {
            const uint32_t st = sbase + ((it + 1) & 1) * STAGEB;
            const int k0 = (it + 1) * GBK;
#pragma unroll
            for (int c = 0; c < 4; c++)
                cp16(st + dst4Row + c * 16, src4 + k0 + c * 8);
#pragma unroll
            for (int j = 0; j < 2; j++)
                cp16(st + dstLRow + (cL + j) * 16, srcL + k0 + (cL + j) * 8);
            CP_COMMIT();
            CP_WAIT(1);
        } else {
            CP_WAIT(0);
        }
        __syncthreads();

        const uint32_t st  = sbase + (it & 1) * STAGEB;
        const uint32_t aS  = st + aWarpOff + aLaneOff;
        const uint32_t bHiS = st + MATB + bWarpOff + bLaneOff;
        const uint32_t bLoS = st + 2 * MATB + bWarpOff + bLaneOff;

#pragma unroll
        for (int ks = 0; ks < 2; ks++) {
            const uint32_t ko = ks * 32;  // 16 fp16 = 32 B per k16 step
            uint32_t aa[2][4], bb[16];
#pragma unroll
            for (int mi = 0; mi < 2; mi++)
                ldsm4(aa[mi], aS + mi * 16 * ROWB + ko);
#pragma unroll
            for (int p = 0; p < 4; p++)
                ldsm4(&bb[p * 4], bHiS + p * 16 * ROWB + ko);
            // term 1: A * Wh
#pragma unroll
            for (int mi = 0; mi < 2; mi++)
#pragma unroll
                for (int nj = 0; nj < 8; nj++)
                    mma_f16(acc[mi][nj], aa[mi], &bb[nj * 2]);
            // reload B buffer with Wl, term 2: A * Wl
#pragma unroll
            for (int p = 0; p < 4; p++)
                ldsm4(&bb[p * 4], bLoS + p * 16 * ROWB + ko);
#pragma unroll
            for (int mi = 0; mi < 2; mi++)
#pragma unroll
                for (int nj = 0; nj < 8; nj++)
                    mma_f16(acc[mi][nj], aa[mi], &bb[nj * 2]);
        }
        __syncthreads();
    }

    // ---- epilogue ----
    const int colBase = n0 + warp_n * 64 + (lane & 3) * 2;
    const int rowBase = m0 + warp_m * 32 + (lane >> 2);
    float bias2[8][2];
#pragma unroll
    for (int nj = 0; nj < 8; nj++) {
        const float* bp = bias + (size_t)s * D_H + colBase + nj * 8;
        bias2[nj][0] = bp[0];
        bias2[nj][1] = bp[1];
    }

#pragma unroll
    for (int mi = 0; mi < 2; mi++) {
#pragma unroll
        for (int h = 0; h < 2; h++) {
            const int row = rowBase + mi * 16 + h * 8;
            const size_t rowOff = ((size_t)s * BATCH + row) * D_H;
#pragma unroll
            for (int nj = 0; nj < 8; nj++) {
                float v0 = fmaxf(acc[mi][nj][2 * h]     + bias2[nj][0], 0.0f);
                float v1 = fmaxf(acc[mi][nj][2 * h + 1] + bias2[nj][1], 0.0f);
                const int n = colBase + nj * 8;
                if (mode == 0) {
                    __half2 hv = __floats2half2_rn(v0, v1);
                    *(__half2*)((__half*)Ch + rowOff + n) = hv;
                } else {
                    *(float2*)(Cf + rowOff + n) = make_float2(v0, v1);
                }
            }
        }
    }
}

// ---------------------------------------------------------------------------
// Last layer (fp32): out[s,b,o] = act[s,b,:] . wl[s,:,o] + bl[s,o]
// ---------------------------------------------------------------------------
__global__ void __launch_bounds__(256) layer_out(
    const float* __restrict__ act, const float* __restrict__ wls,
    const float* __restrict__ bls, float* __restrict__ out)
{
    const int s  = blockIdx.y;
    const int m0 = blockIdx.x * 128;

    __shared__ float As[128][33];
    __shared__ float ws[32 * D_OUT];

    const int tid   = threadIdx.x;
    const int crow  = tid >> 1;
    const int obase = (tid & 1) * 5;

    float acc[5] = {0.f, 0.f, 0.f, 0.f, 0.f};
    const int lr = tid >> 3;
    const int lk = (tid & 7) * 4;

    for (int kt = 0; kt < D_H; kt += 32) {
#pragma unroll
        for (int rr = 0; rr < 4; rr++) {
            int r = lr + rr * 32;
            float4 v = *(const float4*)(act + ((size_t)s * BATCH + m0 + r) * D_H + kt + lk);
            As[r][lk + 0] = v.x; As[r][lk + 1] = v.y; As[r][lk + 2] = v.z; As[r][lk + 3] = v.w;
        }
        for (int i = tid; i < 32 * D_OUT; i += 256)
            ws[i] = wls[(size_t)s * D_H * D_OUT + kt * D_OUT + i];
        __syncthreads();
#pragma unroll
        for (int k = 0; k < 32; k++) {
            float a = As[crow][k];
#pragma unroll
            for (int j = 0; j < 5; j++)
                acc[j] = fmaf(a, ws[k * D_OUT + obase + j], acc[j]);
        }
        __syncthreads();
    }
#pragma unroll
    for (int j = 0; j < 5; j++)
        out[((size_t)s * BATCH + m0 + crow) * D_OUT + obase + j] = acc[j] + bls[s * D_OUT + obase + j];
}

// ---------------------------------------------------------------------------
// kernel_launch
// ---------------------------------------------------------------------------
extern "C" void kernel_launch(void* const* d_in, const int* in_sizes, int n_in,
                              void* d_out, int out_size) {
    const float* x   = (const float*)d_in[0];
    const float* wm0 = (const float*)d_in[1];
    const float* wv0 = (const float*)d_in[2];
    const float* bm0 = (const float*)d_in[3];
    const float* bv0 = (const float*)d_in[4];
    const float* wm1 = (const float*)d_in[5];
    const float* wv1 = (const float*)d_in[6];
    const float* bm1 = (const float*)d_in[7];
    const float* bv1 = (const float*)d_in[8];
    const float* wlm = (const float*)d_in[9];
    const float* wlv = (const float*)d_in[10];
    const float* blm = (const float*)d_in[11];
    const float* blv = (const float*)d_in[12];
    const float* we0 = (const float*)d_in[13];
    const float* be0 = (const float*)d_in[14];
    const float* we1 = (const float*)d_in[15];
    const float* be1 = (const float*)d_in[16];
    const float* wel = (const float*)d_in[17];
    const float* bel = (const float*)d_in[18];
    float* out = (float*)d_out;

    __half *x16, *w0hi, *w0lo, *w1hi, *w1lo, *a016;
    float *act1, *b0, *b1, *wl, *bl;
    cudaGetSymbolAddress((void**)&x16,  g_x16);
    cudaGetSymbolAddress((void**)&w0hi, g_w0hi);
    cudaGetSymbolAddress((void**)&w0lo, g_w0lo);
    cudaGetSymbolAddress((void**)&w1hi, g_w1hi);
    cudaGetSymbolAddress((void**)&w1lo, g_w1lo);
    cudaGetSymbolAddress((void**)&a016, g_a016);
    cudaGetSymbolAddress((void**)&act1, g_act1);
    cudaGetSymbolAddress((void**)&b0,   g_b0);
    cudaGetSymbolAddress((void**)&b1,   g_b1);
    cudaGetSymbolAddress((void**)&wl,   g_wl);
    cudaGetSymbolAddress((void**)&bl,   g_bl);

    static bool attr_set = false;
    if (!attr_set) {
        cudaFuncSetAttribute(gemm_mma, cudaFuncAttributeMaxDynamicSharedMemorySize, SMEM_TOTAL);
        attr_set = true;
    }

    // preps
    {
        int n = BATCH * K0PAD;
        prep_x<<<(n + 255) / 256, 256>>>(x, x16);
    }
    {
        dim3 blk(32, 8);
        dim3 g0(K0PAD / 32, D_H / 32, S_SAMP);
        prep_wt<<<g0, blk>>>(we0, wv0, wm0, w0hi, w0lo, D_IN, D_H, K0PAD);
        dim3 g1(D_H / 32, D_H / 32, S_SAMP);
        prep_wt<<<g1, blk>>>(we1, wv1, wm1, w1hi, w1lo, D_H, D_H, D_H);
    }
    {
        int total = S_SAMP * D_H;
        prep_sample<<<(total + 255) / 256, 256>>>(be0, bv0, bm0, b0, D_H, total);
        prep_sample<<<(total + 255) / 256, 256>>>(be1, bv1, bm1, b1, D_H, total);
    }

    // layer 0: a016 = relu(x16 @ W0 + b0) -> fp16
    {
        dim3 grid(D_H / GBN, BATCH / GBM, S_SAMP);
        gemm_mma<<<grid, 256, SMEM_TOTAL>>>(x16, 0, K0PAD,
                                            w0hi, w0lo, b0,
                                            nullptr, a016, 0);
    }
    // layer 1: act1 = relu(a016 @ W1 + b1) -> fp32
    {
        dim3 grid(D_H / GBN, BATCH / GBM, S_SAMP);
        gemm_mma<<<grid, 256, SMEM_TOTAL>>>(a016, (size_t)BATCH * D_H, D_H,
                                            w1hi, w1lo, b1,
                                            act1, nullptr, 1);
    }
    // last-layer sampling preps + final layer
    {
        int total = S_SAMP * D_H * D_OUT;
        prep_sample<<<(total + 255) / 256, 256>>>(wel, wlv, wlm, wl, D_H * D_OUT, total);
        total = S_SAMP * D_OUT;
        prep_sample<<<(total + 255) / 256, 256>>>(bel, blv, blm, bl, D_OUT, total);
    }
    {
        dim3 grid(BATCH / 128, S_SAMP);
        layer_out<<<grid, 256>>>(act1, wl, bl, out);
    }
}

// round 6
// speedup vs baseline: 1.8966x; 1.3954x over previous
#include <cuda_runtime.h>
#include <cuda_fp16.h>
#include <cstdint>
#include <math.h>

#define S_SAMP 32
#define BATCH  1024
#define D_IN   784
#define D_H    1024
#define D_OUT  10
#define K0PAD  832            // 784 padded to multiple of 32

// ---------------------------------------------------------------------------
// Device scratch (static: no cudaMalloc allowed)
// ---------------------------------------------------------------------------
__device__ __half g_x16[(size_t)BATCH * K0PAD];
__device__ __half g_w016[(size_t)S_SAMP * D_H * K0PAD];   // [S][N][Kpad] transposed
__device__ __half g_w116[(size_t)S_SAMP * D_H * D_H];
__device__ __half g_a016[(size_t)S_SAMP * BATCH * D_H];
__device__ float  g_act1[(size_t)S_SAMP * BATCH * D_H];
__device__ float g_b0[S_SAMP * D_H];
__device__ float g_b1[S_SAMP * D_H];
__device__ float g_wl[S_SAMP * D_H * D_OUT];
__device__ float g_bl[S_SAMP * D_OUT];

// ---------------------------------------------------------------------------
// PTX helpers (arch-neutral only: cp.async, ldmatrix, mma.sync)
// ---------------------------------------------------------------------------
__device__ __forceinline__ uint32_t smem_u32(const void* p) {
    uint32_t a;
    asm("{ .reg .u64 t; cvta.to.shared.u64 t, %1; cvt.u32.u64 %0, t; }" : "=r"(a) : "l"(p));
    return a;
}
__device__ __forceinline__ void cp16(uint32_t dst, const void* src) {
    asm volatile("cp.async.cg.shared.global [%0], [%1], 16;" :: "r"(dst), "l"(src) : "memory");
}
#define CP_COMMIT() asm volatile("cp.async.commit_group;" ::: "memory")
#define CP_WAIT(n)  asm volatile("cp.async.wait_group %0;" :: "n"(n) : "memory")

__device__ __forceinline__ void ldsm4(uint32_t* r, uint32_t addr) {
    asm volatile("ldmatrix.sync.aligned.m8n8.x4.shared.b16 {%0,%1,%2,%3}, [%4];"
        : "=r"(r[0]), "=r"(r[1]), "=r"(r[2]), "=r"(r[3]) : "r"(addr));
}
__device__ __forceinline__ void mma_f16(float* d, const uint32_t* a, const uint32_t* b) {
    asm volatile("mma.sync.aligned.m16n8k16.row.col.f32.f16.f16.f32 "
        "{%0,%1,%2,%3}, {%4,%5,%6,%7}, {%8,%9}, {%0,%1,%2,%3};"
        : "+f"(d[0]), "+f"(d[1]), "+f"(d[2]), "+f"(d[3])
        : "r"(a[0]), "r"(a[1]), "r"(a[2]), "r"(a[3]), "r"(b[0]), "r"(b[1]));
}

// ---------------------------------------------------------------------------
// Prep kernels
// ---------------------------------------------------------------------------
__global__ void prep_x(const float* __restrict__ x, __half* __restrict__ x16) {
    int i = blockIdx.x * blockDim.x + threadIdx.x;
    if (i >= BATCH * K0PAD) return;
    int b = i / K0PAD, k = i - b * K0PAD;
    float v = (k < D_IN) ? x[b * D_IN + k] : 0.0f;
    x16[i] = __float2half(v);
}

// Sample + transpose weights: W[s][n][kpad] = we[s][k][n]*exp(.5 wv[k][n]) + wm[k][n]
__global__ void prep_wt(const float* __restrict__ we, const float* __restrict__ wv,
                        const float* __restrict__ wm,
                        __half* __restrict__ w16,
                        int K, int N, int Kpad) {
    __shared__ float t[32][33];
    int s = blockIdx.z;
    int k0 = blockIdx.x * 32, n0 = blockIdx.y * 32;
    int tx = threadIdx.x, ty = threadIdx.y;       // 32 x 8
#pragma unroll
    for (int i = 0; i < 4; i++) {
        int k = k0 + ty + i * 8;
        float val = 0.0f;
        if (k < K) {
            size_t idx = (size_t)k * N + n0 + tx;
            val = fmaf(we[(size_t)s * K * N + idx], expf(0.5f * wv[idx]), wm[idx]);
        }
        t[ty + i * 8][tx] = val;
    }
    __syncthreads();
#pragma unroll
    for (int i = 0; i < 4; i++) {
        int n = n0 + ty + i * 8;
        float v = t[tx][ty + i * 8];
        size_t off = ((size_t)s * N + n) * Kpad + k0 + tx;
        w16[off] = __float2half(v);
    }
}

__global__ void prep_sample(const float* __restrict__ e, const float* __restrict__ v,
                            const float* __restrict__ m, float* __restrict__ out,
                            int n, int total) {
    int i = blockIdx.x * blockDim.x + threadIdx.x;
    if (i < total) {
        int j = i % n;
        out[i] = fmaf(e[i], expf(0.5f * v[j]), m[j]);
    }
}

// ---------------------------------------------------------------------------
// HMMA GEMM, fp16 single term: C[s] = relu(A16[s] @ W16[s]^T + bias[s])
//   A: fp16 [.][M][Kpad]; W: fp16 [S][N][Kpad] (K-major rows, pre-transposed).
//   CTA tile 128x128x32, 8 warps (warp tile 32x64), double-buffered cp.async.
//   Smem rows padded to 80B (coprime 8 -> LDSM conflict-free).
//   mode 0: write fp16 (feeds next GEMM); mode 1: write fp32.
// ---------------------------------------------------------------------------
#define GBM 128
#define GBN 128
#define GBK 32
#define ROWB 80                      // padded smem row stride (bytes)
#define MATB (128 * ROWB)            // 10240 B per matrix tile
#define STAGEB (2 * MATB)            // A, W = 20480 B
#define SMEM_TOTAL (2 * STAGEB)      // 40960 B

__global__ void __launch_bounds__(256, 2) gemm_mma(
    const __half* __restrict__ A16, size_t aStrideS, int Kpad,
    const __half* __restrict__ W16,
    const float* __restrict__ bias,
    float* __restrict__ Cf, __half* __restrict__ Ch,
    int mode)
{
    extern __shared__ __align__(16) char dynsmem[];
    const uint32_t sbase = smem_u32(dynsmem);

    const int tid  = threadIdx.x;
    const int wid  = tid >> 5;
    const int lane = tid & 31;
    const int s  = blockIdx.z;
    const int m0 = blockIdx.y * GBM;
    const int n0 = blockIdx.x * GBN;

    const int warp_m = wid >> 1;          // 0..3 -> 32-row strip
    const int warp_n = wid & 1;           // 0..1 -> 64-col strip

    const __half* aG = A16 + (size_t)s * aStrideS + (size_t)m0 * Kpad;
    const __half* wG = W16 + ((size_t)s * D_H + n0) * Kpad;

    // Loader: tid 0..127 -> A row tid; tid 128..255 -> W row tid-128; 4 cp16 each
    const int lrow = tid & 127;
    const int firstHalf = (tid < 128);
    const __half* src4 = firstHalf ? (aG + (size_t)lrow * Kpad)
                                   : (wG + (size_t)lrow * Kpad);
    const uint32_t dst4Row = (firstHalf ? 0 : MATB) + (uint32_t)lrow * ROWB;

    // ldmatrix per-lane offsets
    const uint32_t aLaneOff = (uint32_t)(lane & 15) * ROWB + (uint32_t)(lane >> 4) * 16;
    const uint32_t bLaneOff = (uint32_t)((lane & 7) + ((lane & 16) >> 1)) * ROWB
                            + (uint32_t)((lane >> 3) & 1) * 16;
    const uint32_t aWarpOff = (uint32_t)(warp_m * 32) * ROWB;
    const uint32_t bWarpOff = (uint32_t)(warp_n * 64) * ROWB;

    float acc[2][8][4];
#pragma unroll
    for (int i = 0; i < 2; i++)
#pragma unroll
        for (int j = 0; j < 8; j++)
#pragma unroll
            for (int q = 0; q < 4; q++) acc[i][j][q] = 0.0f;

    const int nchunks = Kpad / GBK;

    // prologue: load chunk 0 into stage 0
    {
#pragma unroll
        for (int c = 0; c < 4; c++)
            cp16(sbase + dst4Row + c * 16, src4 + c * 8);
        CP_COMMIT();
    }

    for (int it = 0; it < nchunks; it++) {
        // prefetch next chunk
        if (it + 1 < nchunks) {
            const uint32_t st = sbase + ((it + 1) & 1) * STAGEB;
            const int k0 = (it + 1) * GBK;
#pragma unroll
            for (int c = 0; c < 4; c++)
                cp16(st + dst4Row + c * 16, src4 + k0 + c * 8);
            CP_COMMIT();
            CP_WAIT(1);
        } else {
            CP_WAIT(0);
        }
        __syncthreads();

        const uint32_t st = sbase + (it & 1) * STAGEB;
        const uint32_t aS = st + aWarpOff + aLaneOff;
        const uint32_t bS = st + MATB + bWarpOff + bLaneOff;

#pragma unroll
        for (int ks = 0; ks < 2; ks++) {
            const uint32_t ko = ks * 32;  // 16 fp16 = 32 B per k16 step
            uint32_t aa[2][4], bb[16];
#pragma unroll
            for (int mi = 0; mi < 2; mi++)
                ldsm4(aa[mi], aS + mi * 16 * ROWB + ko);
#pragma unroll
            for (int p = 0; p < 4; p++)
                ldsm4(&bb[p * 4], bS + p * 16 * ROWB + ko);
#pragma unroll
            for (int mi = 0; mi < 2; mi++)
#pragma unroll
                for (int nj = 0; nj < 8; nj++)
                    mma_f16(acc[mi][nj], aa[mi], &bb[nj * 2]);
        }
        __syncthreads();
    }

    // ---- epilogue ----
    const int colBase = n0 + warp_n * 64 + (lane & 3) * 2;
    const int rowBase = m0 + warp_m * 32 + (lane >> 2);
    float bias2[8][2];
#pragma unroll
    for (int nj = 0; nj < 8; nj++) {
        const float* bp = bias + (size_t)s * D_H + colBase + nj * 8;
        bias2[nj][0] = bp[0];
        bias2[nj][1] = bp[1];
    }

#pragma unroll
    for (int mi = 0; mi < 2; mi++) {
#pragma unroll
        for (int h = 0; h < 2; h++) {
            const int row = rowBase + mi * 16 + h * 8;
            const size_t rowOff = ((size_t)s * BATCH + row) * D_H;
#pragma unroll
            for (int nj = 0; nj < 8; nj++) {
                float v0 = fmaxf(acc[mi][nj][2 * h]     + bias2[nj][0], 0.0f);
                float v1 = fmaxf(acc[mi][nj][2 * h + 1] + bias2[nj][1], 0.0f);
                const int n = colBase + nj * 8;
                if (mode == 0) {
                    __half2 hv = __floats2half2_rn(v0, v1);
                    *(__half2*)((__half*)Ch + rowOff + n) = hv;
                } else {
                    *(float2*)(Cf + rowOff + n) = make_float2(v0, v1);
                }
            }
        }
    }
}

// ---------------------------------------------------------------------------
// Last layer (fp32): out[s,b,o] = act[s,b,:] . wl[s,:,o] + bl[s,o]
// ---------------------------------------------------------------------------
__global__ void __launch_bounds__(256) layer_out(
    const float* __restrict__ act, const float* __restrict__ wls,
    const float* __restrict__ bls, float* __restrict__ out)
{
    const int s  = blockIdx.y;
    const int m0 = blockIdx.x * 128;

    __shared__ float As[128][33];
    __shared__ float ws[32 * D_OUT];

    const int tid   = threadIdx.x;
    const int crow  = tid >> 1;
    const int obase = (tid & 1) * 5;

    float acc[5] = {0.f, 0.f, 0.f, 0.f, 0.f};
    const int lr = tid >> 3;
    const int lk = (tid & 7) * 4;

    for (int kt = 0; kt < D_H; kt += 32) {
#pragma unroll
        for (int rr = 0; rr < 4; rr++) {
            int r = lr + rr * 32;
            float4 v = *(const float4*)(act + ((size_t)s * BATCH + m0 + r) * D_H + kt + lk);
            As[r][lk + 0] = v.x; As[r][lk + 1] = v.y; As[r][lk + 2] = v.z; As[r][lk + 3] = v.w;
        }
        for (int i = tid; i < 32 * D_OUT; i += 256)
            ws[i] = wls[(size_t)s * D_H * D_OUT + kt * D_OUT + i];
        __syncthreads();
#pragma unroll
        for (int k = 0; k < 32; k++) {
            float a = As[crow][k];
#pragma unroll
            for (int j = 0; j < 5; j++)
                acc[j] = fmaf(a, ws[k * D_OUT + obase + j], acc[j]);
        }
        __syncthreads();
    }
#pragma unroll
    for (int j = 0; j < 5; j++)
        out[((size_t)s * BATCH + m0 + crow) * D_OUT + obase + j] = acc[j] + bls[s * D_OUT + obase + j];
}

// ---------------------------------------------------------------------------
// kernel_launch
// ---------------------------------------------------------------------------
extern "C" void kernel_launch(void* const* d_in, const int* in_sizes, int n_in,
                              void* d_out, int out_size) {
    const float* x   = (const float*)d_in[0];
    const float* wm0 = (const float*)d_in[1];
    const float* wv0 = (const float*)d_in[2];
    const float* bm0 = (const float*)d_in[3];
    const float* bv0 = (const float*)d_in[4];
    const float* wm1 = (const float*)d_in[5];
    const float* wv1 = (const float*)d_in[6];
    const float* bm1 = (const float*)d_in[7];
    const float* bv1 = (const float*)d_in[8];
    const float* wlm = (const float*)d_in[9];
    const float* wlv = (const float*)d_in[10];
    const float* blm = (const float*)d_in[11];
    const float* blv = (const float*)d_in[12];
    const float* we0 = (const float*)d_in[13];
    const float* be0 = (const float*)d_in[14];
    const float* we1 = (const float*)d_in[15];
    const float* be1 = (const float*)d_in[16];
    const float* wel = (const float*)d_in[17];
    const float* bel = (const float*)d_in[18];
    float* out = (float*)d_out;

    __half *x16, *w016, *w116, *a016;
    float *act1, *b0, *b1, *wl, *bl;
    cudaGetSymbolAddress((void**)&x16,  g_x16);
    cudaGetSymbolAddress((void**)&w016, g_w016);
    cudaGetSymbolAddress((void**)&w116, g_w116);
    cudaGetSymbolAddress((void**)&a016, g_a016);
    cudaGetSymbolAddress((void**)&act1, g_act1);
    cudaGetSymbolAddress((void**)&b0,   g_b0);
    cudaGetSymbolAddress((void**)&b1,   g_b1);
    cudaGetSymbolAddress((void**)&wl,   g_wl);
    cudaGetSymbolAddress((void**)&bl,   g_bl);

    static bool attr_set = false;
    if (!attr_set) {
        cudaFuncSetAttribute(gemm_mma, cudaFuncAttributeMaxDynamicSharedMemorySize, SMEM_TOTAL);
        attr_set = true;
    }

    // preps
    {
        int n = BATCH * K0PAD;
        prep_x<<<(n + 255) / 256, 256>>>(x, x16);
    }
    {
        dim3 blk(32, 8);
        dim3 g0(K0PAD / 32, D_H / 32, S_SAMP);
        prep_wt<<<g0, blk>>>(we0, wv0, wm0, w016, D_IN, D_H, K0PAD);
        dim3 g1(D_H / 32, D_H / 32, S_SAMP);
        prep_wt<<<g1, blk>>>(we1, wv1, wm1, w116, D_H, D_H, D_H);
    }
    {
        int total = S_SAMP * D_H;
        prep_sample<<<(total + 255) / 256, 256>>>(be0, bv0, bm0, b0, D_H, total);
        prep_sample<<<(total + 255) / 256, 256>>>(be1, bv1, bm1, b1, D_H, total);
    }

    // layer 0: a016 = relu(x16 @ W0 + b0) -> fp16
    {
        dim3 grid(D_H / GBN, BATCH / GBM, S_SAMP);
        gemm_mma<<<grid, 256, SMEM_TOTAL>>>(x16, 0, K0PAD,
                                            w016, b0,
                                            nullptr, a016, 0);
    }
    // layer 1: act1 = relu(a016 @ W1 + b1) -> fp32
    {
        dim3 grid(D_H / GBN, BATCH / GBM, S_SAMP);
        gemm_mma<<<grid, 256, SMEM_TOTAL>>>(a016, (size_t)BATCH * D_H, D_H,
                                            w116, b1,
                                            act1, nullptr, 1);
    }
    // last-layer sampling preps + final layer
    {
        int total = S_SAMP * D_H * D_OUT;
        prep_sample<<<(total + 255) / 256, 256>>>(wel, wlv, wlm, wl, D_H * D_OUT, total);
        total = S_SAMP * D_OUT;
        prep_sample<<<(total + 255) / 256, 256>>>(bel, blv, blm, bl, D_OUT, total);
    }
    {
        dim3 grid(BATCH / 128, S_SAMP);
        layer_out<<<grid, 256>>>(act1, wl, bl, out);
    }
}

// round 7
// speedup vs baseline: 2.1581x; 1.1379x over previous
#include <cuda_runtime.h>
#include <cuda_fp16.h>
#include <cstdint>
#include <math.h>

#define S_SAMP 32
#define BATCH  1024
#define D_IN   784
#define D_H    1024
#define D_OUT  10
#define K0PAD  832            // 784 padded to multiple of 32

// ---------------------------------------------------------------------------
// Device scratch (static: no cudaMalloc allowed)
// ---------------------------------------------------------------------------
__device__ __half g_x16[(size_t)BATCH * K0PAD];
__device__ __half g_w016[(size_t)S_SAMP * K0PAD * D_H];   // [S][Kpad][N] natural layout
__device__ __half g_w116[(size_t)S_SAMP * D_H * D_H];
__device__ __half g_a016[(size_t)S_SAMP * BATCH * D_H];
__device__ float  g_act1[(size_t)S_SAMP * BATCH * D_H];
__device__ float g_sig0[(size_t)D_IN * D_H];              // exp(0.5*wv0), shared across s
__device__ float g_sig1[(size_t)D_H * D_H];
__device__ float g_b0[S_SAMP * D_H];
__device__ float g_b1[S_SAMP * D_H];
__device__ float g_wl[S_SAMP * D_H * D_OUT];
__device__ float g_bl[S_SAMP * D_OUT];

// ---------------------------------------------------------------------------
// PTX helpers (arch-neutral only: cp.async, ldmatrix, mma.sync)
// ---------------------------------------------------------------------------
__device__ __forceinline__ uint32_t smem_u32(const void* p) {
    uint32_t a;
    asm("{ .reg .u64 t; cvta.to.shared.u64 t, %1; cvt.u32.u64 %0, t; }" : "=r"(a) : "l"(p));
    return a;
}
__device__ __forceinline__ void cp16(uint32_t dst, const void* src) {
    asm volatile("cp.async.cg.shared.global [%0], [%1], 16;" :: "r"(dst), "l"(src) : "memory");
}
#define CP_COMMIT() asm volatile("cp.async.commit_group;" ::: "memory")
#define CP_WAIT(n)  asm volatile("cp.async.wait_group %0;" :: "n"(n) : "memory")

__device__ __forceinline__ void ldsm4(uint32_t* r, uint32_t addr) {
    asm volatile("ldmatrix.sync.aligned.m8n8.x4.shared.b16 {%0,%1,%2,%3}, [%4];"
        : "=r"(r[0]), "=r"(r[1]), "=r"(r[2]), "=r"(r[3]) : "r"(addr));
}
__device__ __forceinline__ void ldsm4t(uint32_t* r, uint32_t addr) {
    asm volatile("ldmatrix.sync.aligned.m8n8.x4.trans.shared.b16 {%0,%1,%2,%3}, [%4];"
        : "=r"(r[0]), "=r"(r[1]), "=r"(r[2]), "=r"(r[3]) : "r"(addr));
}
__device__ __forceinline__ void mma_f16(float* d, const uint32_t* a, const uint32_t* b) {
    asm volatile("mma.sync.aligned.m16n8k16.row.col.f32.f16.f16.f32 "
        "{%0,%1,%2,%3}, {%4,%5,%6,%7}, {%8,%9}, {%0,%1,%2,%3};"
        : "+f"(d[0]), "+f"(d[1]), "+f"(d[2]), "+f"(d[3])
        : "r"(a[0]), "r"(a[1]), "r"(a[2]), "r"(a[3]), "r"(b[0]), "r"(b[1]));
}

// ---------------------------------------------------------------------------
// Prep kernels
// ---------------------------------------------------------------------------
__global__ void prep_sig(const float* __restrict__ wv, float* __restrict__ sig, int n) {
    int i = blockIdx.x * blockDim.x + threadIdx.x;
    if (i < n) sig[i] = expf(0.5f * wv[i]);
}

__global__ void prep_x(const float* __restrict__ x, __half* __restrict__ x16) {
    int i = blockIdx.x * blockDim.x + threadIdx.x;
    if (i >= BATCH * K0PAD) return;
    int b = i / K0PAD, k = i - b * K0PAD;
    float v = (k < D_IN) ? x[b * D_IN + k] : 0.0f;
    x16[i] = __float2half(v);
}

// Streaming sampled weights (NO transpose, natural [S][Kpad][N] layout):
//   w16[s][k][n] = we[s][k][n] * sig[k][n] + wm[k][n]   (k >= K -> 0)
// 2 elements per thread (half2 store).
__global__ void prep_w(const float* __restrict__ we, const float* __restrict__ sig,
                       const float* __restrict__ wm, __half* __restrict__ w16,
                       int K, int Kpad) {
    int i = blockIdx.x * blockDim.x + threadIdx.x;   // pair index
    int npairs = (S_SAMP * Kpad * D_H) / 2;
    if (i >= npairs) return;
    int ii = i * 2;
    int perS = Kpad * D_H;
    int s = ii / perS;
    int rem = ii - s * perS;
    int k = rem / D_H;
    int n = rem - k * D_H;
    __half2 out;
    if (k < K) {
        size_t widx = ((size_t)s * K + k) * D_H + n;
        int pidx = k * D_H + n;
        float2 e  = *(const float2*)(we + widx);
        float2 sg = *(const float2*)(sig + pidx);
        float2 mm = *(const float2*)(wm + pidx);
        out = __floats2half2_rn(fmaf(e.x, sg.x, mm.x), fmaf(e.y, sg.y, mm.y));
    } else {
        out = __floats2half2_rn(0.0f, 0.0f);
    }
    *(__half2*)(w16 + (size_t)s * perS + rem) = out;
}

__global__ void prep_sample(const float* __restrict__ e, const float* __restrict__ v,
                            const float* __restrict__ m, float* __restrict__ out,
                            int n, int total) {
    int i = blockIdx.x * blockDim.x + threadIdx.x;
    if (i < total) {
        int j = i % n;
        out[i] = fmaf(e[i], expf(0.5f * v[j]), m[j]);
    }
}

// ---------------------------------------------------------------------------
// HMMA GEMM, fp16 single term: C[s] = relu(A16[s] @ W16[s] + bias[s])
//   A: fp16 [.][M][Kpad] row-major; W: fp16 [S][Kpad][N] k-major (natural).
//   B fragments via ldmatrix.x4.trans on k-major W tiles.
//   CTA tile 128x128x32, 8 warps (warp tile 32x64), double-buffered cp.async.
//   mode 0: write fp16 (feeds next GEMM); mode 1: write fp32.
// ---------------------------------------------------------------------------
#define GBM 128
#define GBN 128
#define GBK 32
#define ROWB_A 80                    // A smem row stride (bytes), coprime pad
#define A_MATB (128 * ROWB_A)        // 10240 B
#define ROWB_W 272                   // W smem k-row stride: 256B data + 16 pad
#define W_MATB (32 * ROWB_W)         // 8704 B
#define STAGEB (A_MATB + W_MATB)     // 18944 B
#define SMEM_TOTAL (2 * STAGEB)      // 37888 B

__global__ void __launch_bounds__(256, 2) gemm_mma(
    const __half* __restrict__ A16, size_t aStrideS, int Kpad,
    const __half* __restrict__ W16,
    const float* __restrict__ bias,
    float* __restrict__ Cf, __half* __restrict__ Ch,
    int mode)
{
    extern __shared__ __align__(16) char dynsmem[];
    const uint32_t sbase = smem_u32(dynsmem);

    const int tid  = threadIdx.x;
    const int wid  = tid >> 5;
    const int lane = tid & 31;
    const int s  = blockIdx.z;
    const int m0 = blockIdx.y * GBM;
    const int n0 = blockIdx.x * GBN;

    const int warp_m = wid >> 1;          // 0..3 -> 32-row strip
    const int warp_n = wid & 1;           // 0..1 -> 64-col strip

    const __half* aG = A16 + (size_t)s * aStrideS + (size_t)m0 * Kpad;
    const __half* wG = W16 + (size_t)s * Kpad * D_H + n0;   // k-major rows of N

    // Loaders:
    //   tid 0..127  : A row tid, 4 x cp16 covering 64B (32 fp16)
    //   tid 128..255: W; j = tid-128 -> k-row j>>2, quarter (j&3): 4 x cp16
    const int firstHalf = (tid < 128);
    const int lrowA = tid & 127;
    const int wj    = tid & 127;
    const int wrow  = wj >> 2;
    const int wgrp  = wj & 3;

    // ldmatrix per-lane offsets
    const uint32_t aLaneOff = (uint32_t)(lane & 15) * ROWB_A + (uint32_t)(lane >> 4) * 16
                            + (uint32_t)(warp_m * 32) * ROWB_A;
    const int bm = lane >> 3, br = lane & 7;
    const uint32_t bTransOff = (uint32_t)((bm & 1) * 8 + br) * ROWB_W + (uint32_t)(bm >> 1) * 16
                             + (uint32_t)warp_n * 128;   // warp's 64-col strip (64*2B)

    float acc[2][8][4];
#pragma unroll
    for (int i = 0; i < 2; i++)
#pragma unroll
        for (int j = 0; j < 8; j++)
#pragma unroll
            for (int q = 0; q < 4; q++) acc[i][j][q] = 0.0f;

    const int nchunks = Kpad / GBK;

    // prologue: load chunk 0 into stage 0
    if (firstHalf) {
#pragma unroll
        for (int c = 0; c < 4; c++)
            cp16(sbase + (uint32_t)lrowA * ROWB_A + c * 16, aG + (size_t)lrowA * Kpad + c * 8);
    } else {
#pragma unroll
        for (int c = 0; c < 4; c++)
            cp16(sbase + A_MATB + (uint32_t)wrow * ROWB_W + wgrp * 64 + c * 16,
                 wG + (size_t)wrow * D_H + wgrp * 32 + c * 8);
    }
    CP_COMMIT();

    for (int it = 0; it < nchunks; it++) {
        // prefetch next chunk
        if (it + 1 < nchunks) {
            const uint32_t st = sbase + ((it + 1) & 1) * STAGEB;
            const int k0 = (it + 1) * GBK;
            if (firstHalf) {
#pragma unroll
                for (int c = 0; c < 4; c++)
                    cp16(st + (uint32_t)lrowA * ROWB_A + c * 16,
                         aG + (size_t)lrowA * Kpad + k0 + c * 8);
            } else {
#pragma unroll
                for (int c = 0; c < 4; c++)
                    cp16(st + A_MATB + (uint32_t)wrow * ROWB_W + wgrp * 64 + c * 16,
                         wG + (size_t)(k0 + wrow) * D_H + wgrp * 32 + c * 8);
            }
            CP_COMMIT();
            CP_WAIT(1);
        } else {
            CP_WAIT(0);
        }
        __syncthreads();

        const uint32_t st = sbase + (it & 1) * STAGEB;
        const uint32_t aS = st + aLaneOff;
        const uint32_t bS = st + A_MATB + bTransOff;

#pragma unroll
        for (int ks = 0; ks < 2; ks++) {
            uint32_t aa[2][4], bb[16];
#pragma unroll
            for (int mi = 0; mi < 2; mi++)
                ldsm4(aa[mi], aS + mi * 16 * ROWB_A + ks * 32);
#pragma unroll
            for (int p = 0; p < 4; p++)
                ldsm4t(&bb[p * 4], bS + ks * 16 * ROWB_W + p * 32);
#pragma unroll
            for (int mi = 0; mi < 2; mi++)
#pragma unroll
                for (int nj = 0; nj < 8; nj++)
                    mma_f16(acc[mi][nj], aa[mi], &bb[nj * 2]);
        }
        __syncthreads();
    }

    // ---- epilogue ----
    const int colBase = n0 + warp_n * 64 + (lane & 3) * 2;
    const int rowBase = m0 + warp_m * 32 + (lane >> 2);
    float bias2[8][2];
#pragma unroll
    for (int nj = 0; nj < 8; nj++) {
        const float* bp = bias + (size_t)s * D_H + colBase + nj * 8;
        bias2[nj][0] = bp[0];
        bias2[nj][1] = bp[1];
    }

#pragma unroll
    for (int mi = 0; mi < 2; mi++) {
#pragma unroll
        for (int h = 0; h < 2; h++) {
            const int row = rowBase + mi * 16 + h * 8;
            const size_t rowOff = ((size_t)s * BATCH + row) * D_H;
#pragma unroll
            for (int nj = 0; nj < 8; nj++) {
                float v0 = fmaxf(acc[mi][nj][2 * h]     + bias2[nj][0], 0.0f);
                float v1 = fmaxf(acc[mi][nj][2 * h + 1] + bias2[nj][1], 0.0f);
                const int n = colBase + nj * 8;
                if (mode == 0) {
                    __half2 hv = __floats2half2_rn(v0, v1);
                    *(__half2*)((__half*)Ch + rowOff + n) = hv;
                } else {
                    *(float2*)(Cf + rowOff + n) = make_float2(v0, v1);
                }
            }
        }
    }
}

// ---------------------------------------------------------------------------
// Last layer (fp32): out[s,b,o] = act[s,b,:] . wl[s,:,o] + bl[s,o]
// ---------------------------------------------------------------------------
__global__ void __launch_bounds__(256) layer_out(
    const float* __restrict__ act, const float* __restrict__ wls,
    const float* __restrict__ bls, float* __restrict__ out)
{
    const int s  = blockIdx.y;
    const int m0 = blockIdx.x * 128;

    __shared__ float As[128][33];
    __shared__ float ws[32 * D_OUT];

    const int tid   = threadIdx.x;
    const int crow  = tid >> 1;
    const int obase = (tid & 1) * 5;

    float acc[5] = {0.f, 0.f, 0.f, 0.f, 0.f};
    const int lr = tid >> 3;
    const int lk = (tid & 7) * 4;

    for (int kt = 0; kt < D_H; kt += 32) {
#pragma unroll
        for (int rr = 0; rr < 4; rr++) {
            int r = lr + rr * 32;
            float4 v = *(const float4*)(act + ((size_t)s * BATCH + m0 + r) * D_H + kt + lk);
            As[r][lk + 0] = v.x; As[r][lk + 1] = v.y; As[r][lk + 2] = v.z; As[r][lk + 3] = v.w;
        }
        for (int i = tid; i < 32 * D_OUT; i += 256)
            ws[i] = wls[(size_t)s * D_H * D_OUT + kt * D_OUT + i];
        __syncthreads();
#pragma unroll
        for (int k = 0; k < 32; k++) {
            float a = As[crow][k];
#pragma unroll
            for (int j = 0; j < 5; j++)
                acc[j] = fmaf(a, ws[k * D_OUT + obase + j], acc[j]);
        }
        __syncthreads();
    }
#pragma unroll
    for (int j = 0; j < 5; j++)
        out[((size_t)s * BATCH + m0 + crow) * D_OUT + obase + j] = acc[j] + bls[s * D_OUT + obase + j];
}

// ---------------------------------------------------------------------------
// kernel_launch
// ---------------------------------------------------------------------------
extern "C" void kernel_launch(void* const* d_in, const int* in_sizes, int n_in,
                              void* d_out, int out_size) {
    const float* x   = (const float*)d_in[0];
    const float* wm0 = (const float*)d_in[1];
    const float* wv0 = (const float*)d_in[2];
    const float* bm0 = (const float*)d_in[3];
    const float* bv0 = (const float*)d_in[4];
    const float* wm1 = (const float*)d_in[5];
    const float* wv1 = (const float*)d_in[6];
    const float* bm1 = (const float*)d_in[7];
    const float* bv1 = (const float*)d_in[8];
    const float* wlm = (const float*)d_in[9];
    const float* wlv = (const float*)d_in[10];
    const float* blm = (const float*)d_in[11];
    const float* blv = (const float*)d_in[12];
    const float* we0 = (const float*)d_in[13];
    const float* be0 = (const float*)d_in[14];
    const float* we1 = (const float*)d_in[15];
    const float* be1 = (const float*)d_in[16];
    const float* wel = (const float*)d_in[17];
    const float* bel = (const float*)d_in[18];
    float* out = (float*)d_out;

    __half *x16, *w016, *w116, *a016;
    float *act1, *sig0, *sig1, *b0, *b1, *wl, *bl;
    cudaGetSymbolAddress((void**)&x16,  g_x16);
    cudaGetSymbolAddress((void**)&w016, g_w016);
    cudaGetSymbolAddress((void**)&w116, g_w116);
    cudaGetSymbolAddress((void**)&a016, g_a016);
    cudaGetSymbolAddress((void**)&act1, g_act1);
    cudaGetSymbolAddress((void**)&sig0, g_sig0);
    cudaGetSymbolAddress((void**)&sig1, g_sig1);
    cudaGetSymbolAddress((void**)&b0,   g_b0);
    cudaGetSymbolAddress((void**)&b1,   g_b1);
    cudaGetSymbolAddress((void**)&wl,   g_wl);
    cudaGetSymbolAddress((void**)&bl,   g_bl);

    static bool attr_set = false;
    if (!attr_set) {
        cudaFuncSetAttribute(gemm_mma, cudaFuncAttributeMaxDynamicSharedMemorySize, SMEM_TOTAL);
        attr_set = true;
    }

    // sigmas (once per (k,n), NOT per sample)
    {
        int n = D_IN * D_H;
        prep_sig<<<(n + 255) / 256, 256>>>(wv0, sig0, n);
        n = D_H * D_H;
        prep_sig<<<(n + 255) / 256, 256>>>(wv1, sig1, n);
    }
    // x -> fp16 padded
    {
        int n = BATCH * K0PAD;
        prep_x<<<(n + 255) / 256, 256>>>(x, x16);
    }
    // sampled weights, streaming (no transpose)
    {
        int npairs = S_SAMP * K0PAD * D_H / 2;
        prep_w<<<(npairs + 255) / 256, 256>>>(we0, sig0, wm0, w016, D_IN, K0PAD);
        npairs = S_SAMP * D_H * D_H / 2;
        prep_w<<<(npairs + 255) / 256, 256>>>(we1, sig1, wm1, w116, D_H, D_H);
    }
    // sampled biases
    {
        int total = S_SAMP * D_H;
        prep_sample<<<(total + 255) / 256, 256>>>(be0, bv0, bm0, b0, D_H, total);
        prep_sample<<<(total + 255) / 256, 256>>>(be1, bv1, bm1, b1, D_H, total);
    }

    // layer 0: a016 = relu(x16 @ W0 + b0) -> fp16
    {
        dim3 grid(D_H / GBN, BATCH / GBM, S_SAMP);
        gemm_mma<<<grid, 256, SMEM_TOTAL>>>(x16, 0, K0PAD,
                                            w016, b0,
                                            nullptr, a016, 0);
    }
    // layer 1: act1 = relu(a016 @ W1 + b1) -> fp32
    {
        dim3 grid(D_H / GBN, BATCH / GBM, S_SAMP);
        gemm_mma<<<grid, 256, SMEM_TOTAL>>>(a016, (size_t)BATCH * D_H, D_H,
                                            w116, b1,
                                            act1, nullptr, 1);
    }
    // last-layer sampling preps + final layer
    {
        int total = S_SAMP * D_H * D_OUT;
        prep_sample<<<(total + 255) / 256, 256>>>(wel, wlv, wlm, wl, D_H * D_OUT, total);
        total = S_SAMP * D_OUT;
        prep_sample<<<(total + 255) / 256, 256>>>(bel, blv, blm, bl, D_OUT, total);
    }
    {
        dim3 grid(BATCH / 128, S_SAMP);
        layer_out<<<grid, 256>>>(act1, wl, bl, out);
    }
}

// round 8
// speedup vs baseline: 2.2050x; 1.0217x over previous
#include <cuda_runtime.h>
#include <cuda_fp16.h>
#include <cstdint>
#include <math.h>

#define S_SAMP 32
#define BATCH  1024
#define D_IN   784
#define D_H    1024
#define D_OUT  10
#define K0PAD  832            // 784 padded to multiple of 64

// ---------------------------------------------------------------------------
// Device scratch (static: no cudaMalloc allowed)
// ---------------------------------------------------------------------------
__device__ __half g_x16[(size_t)BATCH * K0PAD];
__device__ __half g_w016[(size_t)S_SAMP * K0PAD * D_H];   // [S][Kpad][N] natural layout
__device__ __half g_w116[(size_t)S_SAMP * D_H * D_H];
__device__ __half g_a016[(size_t)S_SAMP * BATCH * D_H];
__device__ float  g_act1[(size_t)S_SAMP * BATCH * D_H];
__device__ float g_sig0[(size_t)D_IN * D_H];              // exp(0.5*wv0), shared across s
__device__ float g_sig1[(size_t)D_H * D_H];
__device__ float g_b0[S_SAMP * D_H];
__device__ float g_b1[S_SAMP * D_H];
__device__ float g_wl[S_SAMP * D_H * D_OUT];
__device__ float g_bl[S_SAMP * D_OUT];

// ---------------------------------------------------------------------------
// PTX helpers (arch-neutral only: cp.async, ldmatrix, mma.sync)
// ---------------------------------------------------------------------------
__device__ __forceinline__ uint32_t smem_u32(const void* p) {
    uint32_t a;
    asm("{ .reg .u64 t; cvta.to.shared.u64 t, %1; cvt.u32.u64 %0, t; }" : "=r"(a) : "l"(p));
    return a;
}
__device__ __forceinline__ void cp16(uint32_t dst, const void* src) {
    asm volatile("cp.async.cg.shared.global [%0], [%1], 16;" :: "r"(dst), "l"(src) : "memory");
}
#define CP_COMMIT() asm volatile("cp.async.commit_group;" ::: "memory")
#define CP_WAIT(n)  asm volatile("cp.async.wait_group %0;" :: "n"(n) : "memory")

__device__ __forceinline__ void ldsm4(uint32_t* r, uint32_t addr) {
    asm volatile("ldmatrix.sync.aligned.m8n8.x4.shared.b16 {%0,%1,%2,%3}, [%4];"
        : "=r"(r[0]), "=r"(r[1]), "=r"(r[2]), "=r"(r[3]) : "r"(addr));
}
__device__ __forceinline__ void ldsm4t(uint32_t* r, uint32_t addr) {
    asm volatile("ldmatrix.sync.aligned.m8n8.x4.trans.shared.b16 {%0,%1,%2,%3}, [%4];"
        : "=r"(r[0]), "=r"(r[1]), "=r"(r[2]), "=r"(r[3]) : "r"(addr));
}
__device__ __forceinline__ void mma_f16(float* d, const uint32_t* a, const uint32_t* b) {
    asm volatile("mma.sync.aligned.m16n8k16.row.col.f32.f16.f16.f32 "
        "{%0,%1,%2,%3}, {%4,%5,%6,%7}, {%8,%9}, {%0,%1,%2,%3};"
        : "+f"(d[0]), "+f"(d[1]), "+f"(d[2]), "+f"(d[3])
        : "r"(a[0]), "r"(a[1]), "r"(a[2]), "r"(a[3]), "r"(b[0]), "r"(b[1]));
}

// ---------------------------------------------------------------------------
// Prep kernels
// ---------------------------------------------------------------------------
__global__ void prep_sig(const float* __restrict__ wv, float* __restrict__ sig, int n) {
    int i = blockIdx.x * blockDim.x + threadIdx.x;
    if (i < n) sig[i] = expf(0.5f * wv[i]);
}

__global__ void prep_x(const float* __restrict__ x, __half* __restrict__ x16) {
    int i = blockIdx.x * blockDim.x + threadIdx.x;
    if (i >= BATCH * K0PAD) return;
    int b = i / K0PAD, k = i - b * K0PAD;
    float v = (k < D_IN) ? x[b * D_IN + k] : 0.0f;
    x16[i] = __float2half(v);
}

// Streaming sampled weights, [S][Kpad][N] natural layout, 8 elems/thread:
//   w16[s][k][n] = we[s][k][n] * sig[k][n] + wm[k][n]   (k >= K -> 0)
// s from blockIdx.y; k,n via pow2 shifts (D_H = 1024). Pure-streaming FMA.
__global__ void __launch_bounds__(256) prep_w(
    const float* __restrict__ we, const float* __restrict__ sig,
    const float* __restrict__ wm, __half* __restrict__ w16,
    int K, int Kpad)
{
    const int s = blockIdx.y;
    const int i = (blockIdx.x * 256 + threadIdx.x) * 8;   // element index in plane
    if (i >= Kpad * D_H) return;
    const int k = i >> 10;
    const int n = i & 1023;

    uint4 outv;
    if (k < K) {
        const float* weP = we + ((size_t)s * K + k) * D_H + n;
        const float* sgP = sig + k * D_H + n;
        const float* wmP = wm  + k * D_H + n;
        float4 e0 = *(const float4*)(weP);
        float4 e1 = *(const float4*)(weP + 4);
        float4 s0 = *(const float4*)(sgP);
        float4 s1 = *(const float4*)(sgP + 4);
        float4 m0 = *(const float4*)(wmP);
        float4 m1 = *(const float4*)(wmP + 4);
        __half2 h0 = __floats2half2_rn(fmaf(e0.x, s0.x, m0.x), fmaf(e0.y, s0.y, m0.y));
        __half2 h1 = __floats2half2_rn(fmaf(e0.z, s0.z, m0.z), fmaf(e0.w, s0.w, m0.w));
        __half2 h2 = __floats2half2_rn(fmaf(e1.x, s1.x, m1.x), fmaf(e1.y, s1.y, m1.y));
        __half2 h3 = __floats2half2_rn(fmaf(e1.z, s1.z, m1.z), fmaf(e1.w, s1.w, m1.w));
        outv = make_uint4(*(uint32_t*)&h0, *(uint32_t*)&h1, *(uint32_t*)&h2, *(uint32_t*)&h3);
    } else {
        outv = make_uint4(0, 0, 0, 0);
    }
    *(uint4*)(w16 + (size_t)s * Kpad * D_H + i) = outv;
}

__global__ void prep_sample(const float* __restrict__ e, const float* __restrict__ v,
                            const float* __restrict__ m, float* __restrict__ out,
                            int n, int total) {
    int i = blockIdx.x * blockDim.x + threadIdx.x;
    if (i < total) {
        int j = i % n;
        out[i] = fmaf(e[i], expf(0.5f * v[j]), m[j]);
    }
}

// ---------------------------------------------------------------------------
// HMMA GEMM, fp16 single term: C[s] = relu(A16[s] @ W16[s] + bias[s])
//   A: fp16 [.][M][Kpad] row-major; W: fp16 [S][Kpad][N] k-major (natural).
//   B fragments via ldmatrix.x4.trans on k-major W tiles.
//   CTA tile 128x128x64, 8 warps (warp tile 32x64), double-buffered cp.async.
//   mode 0: write fp16 (feeds next GEMM); mode 1: write fp32.
// ---------------------------------------------------------------------------
#define GBM 128
#define GBN 128
#define GBK 64
#define ROWB_A 144                   // A smem row stride: 128B data + 16 pad (9x16, coprime 8)
#define A_MATB (128 * ROWB_A)        // 18432 B
#define ROWB_W 272                   // W smem k-row stride: 256B data + 16 pad (17x16)
#define W_MATB (64 * ROWB_W)         // 17408 B
#define STAGEB (A_MATB + W_MATB)     // 35840 B
#define SMEM_TOTAL (2 * STAGEB)      // 71680 B

__global__ void __launch_bounds__(256, 2) gemm_mma(
    const __half* __restrict__ A16, size_t aStrideS, int Kpad,
    const __half* __restrict__ W16,
    const float* __restrict__ bias,
    float* __restrict__ Cf, __half* __restrict__ Ch,
    int mode)
{
    extern __shared__ __align__(16) char dynsmem[];
    const uint32_t sbase = smem_u32(dynsmem);

    const int tid  = threadIdx.x;
    const int wid  = tid >> 5;
    const int lane = tid & 31;
    const int s  = blockIdx.z;
    const int m0 = blockIdx.y * GBM;
    const int n0 = blockIdx.x * GBN;

    const int warp_m = wid >> 1;          // 0..3 -> 32-row strip
    const int warp_n = wid & 1;           // 0..1 -> 64-col strip

    const __half* aG = A16 + (size_t)s * aStrideS + (size_t)m0 * Kpad;
    const __half* wG = W16 + (size_t)s * Kpad * D_H + n0;   // k-major rows of N

    // Loaders (per chunk: A 128 rows x 128B, W 64 rows x 256B; 8 cp16/thread):
    //   tid 0..127  : A row tid, 8 x cp16
    //   tid 128..255: W; wj = tid-128 -> k-row wj>>1, half (wj&1): 8 x cp16
    const int firstHalf = (tid < 128);
    const int lrowA = tid & 127;
    const int wj    = tid & 127;
    const int wrow  = wj >> 1;
    const int wgrp  = wj & 1;

    // ldmatrix per-lane offsets
    const uint32_t aLaneOff = (uint32_t)(lane & 15) * ROWB_A + (uint32_t)(lane >> 4) * 16
                            + (uint32_t)(warp_m * 32) * ROWB_A;
    const int bm = lane >> 3, br = lane & 7;
    const uint32_t bTransOff = (uint32_t)((bm & 1) * 8 + br) * ROWB_W + (uint32_t)(bm >> 1) * 16
                             + (uint32_t)warp_n * 128;   // warp's 64-col strip (64*2B)

    float acc[2][8][4];
#pragma unroll
    for (int i = 0; i < 2; i++)
#pragma unroll
        for (int j = 0; j < 8; j++)
#pragma unroll
            for (int q = 0; q < 4; q++) acc[i][j][q] = 0.0f;

    const int nchunks = Kpad / GBK;

    // prologue: load chunk 0 into stage 0
    if (firstHalf) {
#pragma unroll
        for (int c = 0; c < 8; c++)
            cp16(sbase + (uint32_t)lrowA * ROWB_A + c * 16, aG + (size_t)lrowA * Kpad + c * 8);
    } else {
#pragma unroll
        for (int c = 0; c < 8; c++)
            cp16(sbase + A_MATB + (uint32_t)wrow * ROWB_W + wgrp * 128 + c * 16,
                 wG + (size_t)wrow * D_H + wgrp * 64 + c * 8);
    }
    CP_COMMIT();

    for (int it = 0; it < nchunks; it++) {
        // prefetch next chunk
        if (it + 1 < nchunks) {
            const uint32_t st = sbase + ((it + 1) & 1) * STAGEB;
            const int k0 = (it + 1) * GBK;
            if (firstHalf) {
#pragma unroll
                for (int c = 0; c < 8; c++)
                    cp16(st + (uint32_t)lrowA * ROWB_A + c * 16,
                         aG + (size_t)lrowA * Kpad + k0 + c * 8);
            } else {
#pragma unroll
                for (int c = 0; c < 8; c++)
                    cp16(st + A_MATB + (uint32_t)wrow * ROWB_W + wgrp * 128 + c * 16,
                         wG + (size_t)(k0 + wrow) * D_H + wgrp * 64 + c * 8);
            }
            CP_COMMIT();
            CP_WAIT(1);
        } else {
            CP_WAIT(0);
        }
        __syncthreads();

        const uint32_t st = sbase + (it & 1) * STAGEB;
        const uint32_t aS = st + aLaneOff;
        const uint32_t bS = st + A_MATB + bTransOff;

#pragma unroll
        for (int ks = 0; ks < 4; ks++) {
            uint32_t aa[2][4], bb[16];
#pragma unroll
            for (int mi = 0; mi < 2; mi++)
                ldsm4(aa[mi], aS + mi * 16 * ROWB_A + ks * 32);
#pragma unroll
            for (int p = 0; p < 4; p++)
                ldsm4t(&bb[p * 4], bS + ks * 16 * ROWB_W + p * 32);
#pragma unroll
            for (int mi = 0; mi < 2; mi++)
#pragma unroll
                for (int nj = 0; nj < 8; nj++)
                    mma_f16(acc[mi][nj], aa[mi], &bb[nj * 2]);
        }
        __syncthreads();
    }

    // ---- epilogue ----
    const int colBase = n0 + warp_n * 64 + (lane & 3) * 2;
    const int rowBase = m0 + warp_m * 32 + (lane >> 2);
    float bias2[8][2];
#pragma unroll
    for (int nj = 0; nj < 8; nj++) {
        const float* bp = bias + (size_t)s * D_H + colBase + nj * 8;
        bias2[nj][0] = bp[0];
        bias2[nj][1] = bp[1];
    }

#pragma unroll
    for (int mi = 0; mi < 2; mi++) {
#pragma unroll
        for (int h = 0; h < 2; h++) {
            const int row = rowBase + mi * 16 + h * 8;
            const size_t rowOff = ((size_t)s * BATCH + row) * D_H;
#pragma unroll
            for (int nj = 0; nj < 8; nj++) {
                float v0 = fmaxf(acc[mi][nj][2 * h]     + bias2[nj][0], 0.0f);
                float v1 = fmaxf(acc[mi][nj][2 * h + 1] + bias2[nj][1], 0.0f);
                const int n = colBase + nj * 8;
                if (mode == 0) {
                    __half2 hv = __floats2half2_rn(v0, v1);
                    *(__half2*)((__half*)Ch + rowOff + n) = hv;
                } else {
                    *(float2*)(Cf + rowOff + n) = make_float2(v0, v1);
                }
            }
        }
    }
}

// ---------------------------------------------------------------------------
// Last layer (fp32): out[s,b,o] = act[s,b,:] . wl[s,:,o] + bl[s,o]
// ---------------------------------------------------------------------------
__global__ void __launch_bounds__(256) layer_out(
    const float* __restrict__ act, const float* __restrict__ wls,
    const float* __restrict__ bls, float* __restrict__ out)
{
    const int s  = blockIdx.y;
    const int m0 = blockIdx.x * 128;

    __shared__ float As[128][33];
    __shared__ float ws[32 * D_OUT];

    const int tid   = threadIdx.x;
    const int crow  = tid >> 1;
    const int obase = (tid & 1) * 5;

    float acc[5] = {0.f, 0.f, 0.f, 0.f, 0.f};
    const int lr = tid >> 3;
    const int lk = (tid & 7) * 4;

    for (int kt = 0; kt < D_H; kt += 32) {
#pragma unroll
        for (int rr = 0; rr < 4; rr++) {
            int r = lr + rr * 32;
            float4 v = *(const float4*)(act + ((size_t)s * BATCH + m0 + r) * D_H + kt + lk);
            As[r][lk + 0] = v.x; As[r][lk + 1] = v.y; As[r][lk + 2] = v.z; As[r][lk + 3] = v.w;
        }
        for (int i = tid; i < 32 * D_OUT; i += 256)
            ws[i] = wls[(size_t)s * D_H * D_OUT + kt * D_OUT + i];
        __syncthreads();
#pragma unroll
        for (int k = 0; k < 32; k++) {
            float a = As[crow][k];
#pragma unroll
            for (int j = 0; j < 5; j++)
                acc[j] = fmaf(a, ws[k * D_OUT + obase + j], acc[j]);
        }
        __syncthreads();
    }
#pragma unroll
    for (int j = 0; j < 5; j++)
        out[((size_t)s * BATCH + m0 + crow) * D_OUT + obase + j] = acc[j] + bls[s * D_OUT + obase + j];
}

// ---------------------------------------------------------------------------
// kernel_launch — order chosen so launch 5 (ncu -s 5 -c 1) is gemm L0:
//   0 sig0, 1 sig1, 2 x, 3 b0, 4 w0, 5 GEMM0, 6 w1, 7 b1, 8 GEMM1, 9-10 wl/bl, 11 out
// ---------------------------------------------------------------------------
extern "C" void kernel_launch(void* const* d_in, const int* in_sizes, int n_in,
                              void* d_out, int out_size) {
    const float* x   = (const float*)d_in[0];
    const float* wm0 = (const float*)d_in[1];
    const float* wv0 = (const float*)d_in[2];
    const float* bm0 = (const float*)d_in[3];
    const float* bv0 = (const float*)d_in[4];
    const float* wm1 = (const float*)d_in[5];
    const float* wv1 = (const float*)d_in[6];
    const float* bm1 = (const float*)d_in[7];
    const float* bv1 = (const float*)d_in[8];
    const float* wlm = (const float*)d_in[9];
    const float* wlv = (const float*)d_in[10];
    const float* blm = (const float*)d_in[11];
    const float* blv = (const float*)d_in[12];
    const float* we0 = (const float*)d_in[13];
    const float* be0 = (const float*)d_in[14];
    const float* we1 = (const float*)d_in[15];
    const float* be1 = (const float*)d_in[16];
    const float* wel = (const float*)d_in[17];
    const float* bel = (const float*)d_in[18];
    float* out = (float*)d_out;

    __half *x16, *w016, *w116, *a016;
    float *act1, *sig0, *sig1, *b0, *b1, *wl, *bl;
    cudaGetSymbolAddress((void**)&x16,  g_x16);
    cudaGetSymbolAddress((void**)&w016, g_w016);
    cudaGetSymbolAddress((void**)&w116, g_w116);
    cudaGetSymbolAddress((void**)&a016, g_a016);
    cudaGetSymbolAddress((void**)&act1, g_act1);
    cudaGetSymbolAddress((void**)&sig0, g_sig0);
    cudaGetSymbolAddress((void**)&sig1, g_sig1);
    cudaGetSymbolAddress((void**)&b0,   g_b0);
    cudaGetSymbolAddress((void**)&b1,   g_b1);
    cudaGetSymbolAddress((void**)&wl,   g_wl);
    cudaGetSymbolAddress((void**)&bl,   g_bl);

    static bool attr_set = false;
    if (!attr_set) {
        cudaFuncSetAttribute(gemm_mma, cudaFuncAttributeMaxDynamicSharedMemorySize, SMEM_TOTAL);
        attr_set = true;
    }

    // 0,1: sigmas (once per (k,n), NOT per sample)
    {
        int n = D_IN * D_H;
        prep_sig<<<(n + 255) / 256, 256>>>(wv0, sig0, n);
        n = D_H * D_H;
        prep_sig<<<(n + 255) / 256, 256>>>(wv1, sig1, n);
    }
    // 2: x -> fp16 padded
    {
        int n = BATCH * K0PAD;
        prep_x<<<(n + 255) / 256, 256>>>(x, x16);
    }
    // 3: bias 0
    {
        int total = S_SAMP * D_H;
        prep_sample<<<(total + 255) / 256, 256>>>(be0, bv0, bm0, b0, D_H, total);
    }
    // 4: sampled W0 (streaming, no transpose)
    {
        dim3 grid(K0PAD * D_H / (256 * 8), S_SAMP);
        prep_w<<<grid, 256>>>(we0, sig0, wm0, w016, D_IN, K0PAD);
    }
    // 5: layer 0 GEMM (ncu -s 5 -c 1 lands here)
    {
        dim3 grid(D_H / GBN, BATCH / GBM, S_SAMP);
        gemm_mma<<<grid, 256, SMEM_TOTAL>>>(x16, 0, K0PAD,
                                            w016, b0,
                                            nullptr, a016, 0);
    }
    // 6: sampled W1;  7: bias 1
    {
        dim3 grid(D_H * D_H / (256 * 8), S_SAMP);
        prep_w<<<grid, 256>>>(we1, sig1, wm1, w116, D_H, D_H);
        int total = S_SAMP * D_H;
        prep_sample<<<(total + 255) / 256, 256>>>(be1, bv1, bm1, b1, D_H, total);
    }
    // 8: layer 1 GEMM
    {
        dim3 grid(D_H / GBN, BATCH / GBM, S_SAMP);
        gemm_mma<<<grid, 256, SMEM_TOTAL>>>(a016, (size_t)BATCH * D_H, D_H,
                                            w116, b1,
                                            act1, nullptr, 1);
    }
    // 9,10: last-layer sampling preps; 11: final layer
    {
        int total = S_SAMP * D_H * D_OUT;
        prep_sample<<<(total + 255) / 256, 256>>>(wel, wlv, wlm, wl, D_H * D_OUT, total);
        total = S_SAMP * D_OUT;
        prep_sample<<<(total + 255) / 256, 256>>>(bel, blv, blm, bl, D_OUT, total);
    }
    {
        dim3 grid(BATCH / 128, S_SAMP);
        layer_out<<<grid, 256>>>(act1, wl, bl, out);
    }
}

// round 9
// speedup vs baseline: 2.2294x; 1.0111x over previous
#include <cuda_runtime.h>
#include <cuda_fp16.h>
#include <cstdint>
#include <math.h>

#define S_SAMP 32
#define BATCH  1024
#define D_IN   784
#define D_H    1024
#define D_OUT  10
#define K0PAD  832            // 784 padded to multiple of 64

// ---------------------------------------------------------------------------
// Device scratch (static: no cudaMalloc allowed)
// ---------------------------------------------------------------------------
__device__ __half g_x16[(size_t)BATCH * K0PAD];
__device__ __half g_w016[(size_t)S_SAMP * K0PAD * D_H];   // [S][Kpad][N] natural layout
__device__ __half g_w116[(size_t)S_SAMP * D_H * D_H];
__device__ __half g_a016[(size_t)S_SAMP * BATCH * D_H];
__device__ __half g_a116[(size_t)S_SAMP * BATCH * D_H];   // fp16 act1 (was fp32)
__device__ float g_sig0[(size_t)D_IN * D_H];              // exp(0.5*wv0), shared across s
__device__ float g_sig1[(size_t)D_H * D_H];
__device__ float g_b0[S_SAMP * D_H];
__device__ float g_b1[S_SAMP * D_H];
__device__ float g_wl[S_SAMP * D_H * D_OUT];
__device__ float g_bl[S_SAMP * D_OUT];

// ---------------------------------------------------------------------------
// PTX helpers (arch-neutral only: cp.async, ldmatrix, mma.sync)
// ---------------------------------------------------------------------------
__device__ __forceinline__ uint32_t smem_u32(const void* p) {
    uint32_t a;
    asm("{ .reg .u64 t; cvta.to.shared.u64 t, %1; cvt.u32.u64 %0, t; }" : "=r"(a) : "l"(p));
    return a;
}
__device__ __forceinline__ void cp16(uint32_t dst, const void* src) {
    asm volatile("cp.async.cg.shared.global [%0], [%1], 16;" :: "r"(dst), "l"(src) : "memory");
}
#define CP_COMMIT() asm volatile("cp.async.commit_group;" ::: "memory")
#define CP_WAIT(n)  asm volatile("cp.async.wait_group %0;" :: "n"(n) : "memory")

__device__ __forceinline__ void ldsm4(uint32_t* r, uint32_t addr) {
    asm volatile("ldmatrix.sync.aligned.m8n8.x4.shared.b16 {%0,%1,%2,%3}, [%4];"
        : "=r"(r[0]), "=r"(r[1]), "=r"(r[2]), "=r"(r[3]) : "r"(addr));
}
__device__ __forceinline__ void ldsm4t(uint32_t* r, uint32_t addr) {
    asm volatile("ldmatrix.sync.aligned.m8n8.x4.trans.shared.b16 {%0,%1,%2,%3}, [%4];"
        : "=r"(r[0]), "=r"(r[1]), "=r"(r[2]), "=r"(r[3]) : "r"(addr));
}
__device__ __forceinline__ void mma_f16(float* d, const uint32_t* a, const uint32_t* b) {
    asm volatile("mma.sync.aligned.m16n8k16.row.col.f32.f16.f16.f32 "
        "{%0,%1,%2,%3}, {%4,%5,%6,%7}, {%8,%9}, {%0,%1,%2,%3};"
        : "+f"(d[0]), "+f"(d[1]), "+f"(d[2]), "+f"(d[3])
        : "r"(a[0]), "r"(a[1]), "r"(a[2]), "r"(a[3]), "r"(b[0]), "r"(b[1]));
}

// ---------------------------------------------------------------------------
// Prep kernels
// ---------------------------------------------------------------------------
__global__ void prep_sig(const float* __restrict__ wv, float* __restrict__ sig, int n) {
    int i = blockIdx.x * blockDim.x + threadIdx.x;
    if (i < n) sig[i] = expf(0.5f * wv[i]);
}

__global__ void prep_x(const float* __restrict__ x, __half* __restrict__ x16) {
    int i = blockIdx.x * blockDim.x + threadIdx.x;
    if (i >= BATCH * K0PAD) return;
    int b = i / K0PAD, k = i - b * K0PAD;
    float v = (k < D_IN) ? x[b * D_IN + k] : 0.0f;
    x16[i] = __float2half(v);
}

// Streaming sampled weights, [S][Kpad][N] natural layout, 8 elems/thread:
//   w16[s][k][n] = we[s][k][n] * sig[k][n] + wm[k][n]   (k >= K -> 0)
__global__ void __launch_bounds__(256) prep_w(
    const float* __restrict__ we, const float* __restrict__ sig,
    const float* __restrict__ wm, __half* __restrict__ w16,
    int K, int Kpad)
{
    const int s = blockIdx.y;
    const int i = (blockIdx.x * 256 + threadIdx.x) * 8;   // element index in plane
    if (i >= Kpad * D_H) return;
    const int k = i >> 10;
    const int n = i & 1023;

    uint4 outv;
    if (k < K) {
        const float* weP = we + ((size_t)s * K + k) * D_H + n;
        const float* sgP = sig + k * D_H + n;
        const float* wmP = wm  + k * D_H + n;
        float4 e0 = *(const float4*)(weP);
        float4 e1 = *(const float4*)(weP + 4);
        float4 s0 = *(const float4*)(sgP);
        float4 s1 = *(const float4*)(sgP + 4);
        float4 m0 = *(const float4*)(wmP);
        float4 m1 = *(const float4*)(wmP + 4);
        __half2 h0 = __floats2half2_rn(fmaf(e0.x, s0.x, m0.x), fmaf(e0.y, s0.y, m0.y));
        __half2 h1 = __floats2half2_rn(fmaf(e0.z, s0.z, m0.z), fmaf(e0.w, s0.w, m0.w));
        __half2 h2 = __floats2half2_rn(fmaf(e1.x, s1.x, m1.x), fmaf(e1.y, s1.y, m1.y));
        __half2 h3 = __floats2half2_rn(fmaf(e1.z, s1.z, m1.z), fmaf(e1.w, s1.w, m1.w));
        outv = make_uint4(*(uint32_t*)&h0, *(uint32_t*)&h1, *(uint32_t*)&h2, *(uint32_t*)&h3);
    } else {
        outv = make_uint4(0, 0, 0, 0);
    }
    *(uint4*)(w16 + (size_t)s * Kpad * D_H + i) = outv;
}

__global__ void prep_sample(const float* __restrict__ e, const float* __restrict__ v,
                            const float* __restrict__ m, float* __restrict__ out,
                            int n, int total) {
    int i = blockIdx.x * blockDim.x + threadIdx.x;
    if (i < total) {
        int j = i % n;
        out[i] = fmaf(e[i], expf(0.5f * v[j]), m[j]);
    }
}

// ---------------------------------------------------------------------------
// HMMA GEMM, fp16 single term, 3-stage cp.async pipeline:
//   C[s] = relu(A16[s] @ W16[s] + bias[s]) -> fp16
//   A: fp16 [.][M][Kpad] row-major; W: fp16 [S][Kpad][N] k-major (natural).
//   B fragments via ldmatrix.x4.trans.
//   CTA tile 128x128x64, 8 warps (warp tile 32x64).
// ---------------------------------------------------------------------------
#define GBM 128
#define GBN 128
#define GBK 64
#define NSTAGE 3
#define ROWB_A 144                   // A smem row stride: 128B data + 16 pad
#define A_MATB (128 * ROWB_A)        // 18432 B
#define ROWB_W 272                   // W smem k-row stride: 256B data + 16 pad
#define W_MATB (64 * ROWB_W)         // 17408 B
#define STAGEB (A_MATB + W_MATB)     // 35840 B
#define SMEM_TOTAL (NSTAGE * STAGEB) // 107520 B

__global__ void __launch_bounds__(256, 2) gemm_mma(
    const __half* __restrict__ A16, size_t aStrideS, int Kpad,
    const __half* __restrict__ W16,
    const float* __restrict__ bias,
    __half* __restrict__ Ch)
{
    extern __shared__ __align__(16) char dynsmem[];
    const uint32_t sbase = smem_u32(dynsmem);

    const int tid  = threadIdx.x;
    const int wid  = tid >> 5;
    const int lane = tid & 31;
    const int s  = blockIdx.z;
    const int m0 = blockIdx.y * GBM;
    const int n0 = blockIdx.x * GBN;

    const int warp_m = wid >> 1;          // 0..3 -> 32-row strip
    const int warp_n = wid & 1;           // 0..1 -> 64-col strip

    const __half* aG = A16 + (size_t)s * aStrideS + (size_t)m0 * Kpad;
    const __half* wG = W16 + (size_t)s * Kpad * D_H + n0;   // k-major rows of N

    // Loaders (per chunk: A 128 rows x 128B, W 64 rows x 256B; 8 cp16/thread)
    const int firstHalf = (tid < 128);
    const int lrowA = tid & 127;
    const int wj    = tid & 127;
    const int wrow  = wj >> 1;
    const int wgrp  = wj & 1;

    auto load_chunk = [&](uint32_t st, int k0) {
        if (firstHalf) {
#pragma unroll
            for (int c = 0; c < 8; c++)
                cp16(st + (uint32_t)lrowA * ROWB_A + c * 16,
                     aG + (size_t)lrowA * Kpad + k0 + c * 8);
        } else {
#pragma unroll
            for (int c = 0; c < 8; c++)
                cp16(st + A_MATB + (uint32_t)wrow * ROWB_W + wgrp * 128 + c * 16,
                     wG + (size_t)(k0 + wrow) * D_H + wgrp * 64 + c * 8);
        }
        CP_COMMIT();
    };

    // ldmatrix per-lane offsets
    const uint32_t aLaneOff = (uint32_t)(lane & 15) * ROWB_A + (uint32_t)(lane >> 4) * 16
                            + (uint32_t)(warp_m * 32) * ROWB_A;
    const int bm = lane >> 3, br = lane & 7;
    const uint32_t bTransOff = (uint32_t)((bm & 1) * 8 + br) * ROWB_W + (uint32_t)(bm >> 1) * 16
                             + (uint32_t)warp_n * 128;   // warp's 64-col strip (64*2B)

    float acc[2][8][4];
#pragma unroll
    for (int i = 0; i < 2; i++)
#pragma unroll
        for (int j = 0; j < 8; j++)
#pragma unroll
            for (int q = 0; q < 4; q++) acc[i][j][q] = 0.0f;

    const int nchunks = Kpad / GBK;

    // prologue: load chunks 0,1
    load_chunk(sbase, 0);
    if (nchunks > 1) load_chunk(sbase + STAGEB, GBK);

    int stage = 0;
    for (int it = 0; it < nchunks; it++) {
        // prefetch chunk it+2 into stage (it+2)%3 (== stage (it-1)%3, free since
        // its readers finished before the barrier that ended iteration it-1)
        if (it + 2 < nchunks) {
            int pst = stage + 2; if (pst >= NSTAGE) pst -= NSTAGE;
            load_chunk(sbase + (uint32_t)pst * STAGEB, (it + 2) * GBK);
            CP_WAIT(2);
        } else if (it + 1 < nchunks) {
            CP_WAIT(1);
        } else {
            CP_WAIT(0);
        }
        __syncthreads();

        const uint32_t st = sbase + (uint32_t)stage * STAGEB;
        const uint32_t aS = st + aLaneOff;
        const uint32_t bS = st + A_MATB + bTransOff;

#pragma unroll
        for (int ks = 0; ks < 4; ks++) {
            uint32_t aa[2][4], bb[16];
#pragma unroll
            for (int mi = 0; mi < 2; mi++)
                ldsm4(aa[mi], aS + mi * 16 * ROWB_A + ks * 32);
#pragma unroll
            for (int p = 0; p < 4; p++)
                ldsm4t(&bb[p * 4], bS + ks * 16 * ROWB_W + p * 32);
#pragma unroll
            for (int mi = 0; mi < 2; mi++)
#pragma unroll
                for (int nj = 0; nj < 8; nj++)
                    mma_f16(acc[mi][nj], aa[mi], &bb[nj * 2]);
        }
        __syncthreads();
        if (++stage >= NSTAGE) stage = 0;
    }

    // ---- epilogue: bias + relu -> fp16 ----
    const int colBase = n0 + warp_n * 64 + (lane & 3) * 2;
    const int rowBase = m0 + warp_m * 32 + (lane >> 2);
    float bias2[8][2];
#pragma unroll
    for (int nj = 0; nj < 8; nj++) {
        const float* bp = bias + (size_t)s * D_H + colBase + nj * 8;
        bias2[nj][0] = bp[0];
        bias2[nj][1] = bp[1];
    }

#pragma unroll
    for (int mi = 0; mi < 2; mi++) {
#pragma unroll
        for (int h = 0; h < 2; h++) {
            const int row = rowBase + mi * 16 + h * 8;
            const size_t rowOff = ((size_t)s * BATCH + row) * D_H;
#pragma unroll
            for (int nj = 0; nj < 8; nj++) {
                float v0 = fmaxf(acc[mi][nj][2 * h]     + bias2[nj][0], 0.0f);
                float v1 = fmaxf(acc[mi][nj][2 * h + 1] + bias2[nj][1], 0.0f);
                __half2 hv = __floats2half2_rn(v0, v1);
                *(__half2*)(Ch + rowOff + colBase + nj * 8) = hv;
            }
        }
    }
}

// ---------------------------------------------------------------------------
// Last layer: out[s,b,o] = act16[s,b,:] . wl[s,:,o] + bl[s,o]   (fp16 act)
// ---------------------------------------------------------------------------
__global__ void __launch_bounds__(256) layer_out(
    const __half* __restrict__ act, const float* __restrict__ wls,
    const float* __restrict__ bls, float* __restrict__ out)
{
    const int s  = blockIdx.y;
    const int m0 = blockIdx.x * 128;

    __shared__ float As[128][33];
    __shared__ float ws[32 * D_OUT];

    const int tid   = threadIdx.x;
    const int crow  = tid >> 1;
    const int obase = (tid & 1) * 5;

    float acc[5] = {0.f, 0.f, 0.f, 0.f, 0.f};
    const int lr = tid >> 2;             // 0..63
    const int lk = (tid & 3) * 8;        // 0,8,16,24

    for (int kt = 0; kt < D_H; kt += 32) {
#pragma unroll
        for (int rr = 0; rr < 2; rr++) {
            int r = lr + rr * 64;
            uint4 v = *(const uint4*)(act + ((size_t)s * BATCH + m0 + r) * D_H + kt + lk);
            const __half2* hp = (const __half2*)&v;
#pragma unroll
            for (int q = 0; q < 4; q++) {
                float2 f = __half22float2(hp[q]);
                As[r][lk + 2 * q]     = f.x;
                As[r][lk + 2 * q + 1] = f.y;
            }
        }
        for (int i = tid; i < 32 * D_OUT; i += 256)
            ws[i] = wls[(size_t)s * D_H * D_OUT + kt * D_OUT + i];
        __syncthreads();
#pragma unroll
        for (int k = 0; k < 32; k++) {
            float a = As[crow][k];
#pragma unroll
            for (int j = 0; j < 5; j++)
                acc[j] = fmaf(a, ws[k * D_OUT + obase + j], acc[j]);
        }
        __syncthreads();
    }
#pragma unroll
    for (int j = 0; j < 5; j++)
        out[((size_t)s * BATCH + m0 + crow) * D_OUT + obase + j] = acc[j] + bls[s * D_OUT + obase + j];
}

// ---------------------------------------------------------------------------
// kernel_launch
// ---------------------------------------------------------------------------
extern "C" void kernel_launch(void* const* d_in, const int* in_sizes, int n_in,
                              void* d_out, int out_size) {
    const float* x   = (const float*)d_in[0];
    const float* wm0 = (const float*)d_in[1];
    const float* wv0 = (const float*)d_in[2];
    const float* bm0 = (const float*)d_in[3];
    const float* bv0 = (const float*)d_in[4];
    const float* wm1 = (const float*)d_in[5];
    const float* wv1 = (const float*)d_in[6];
    const float* bm1 = (const float*)d_in[7];
    const float* bv1 = (const float*)d_in[8];
    const float* wlm = (const float*)d_in[9];
    const float* wlv = (const float*)d_in[10];
    const float* blm = (const float*)d_in[11];
    const float* blv = (const float*)d_in[12];
    const float* we0 = (const float*)d_in[13];
    const float* be0 = (const float*)d_in[14];
    const float* we1 = (const float*)d_in[15];
    const float* be1 = (const float*)d_in[16];
    const float* wel = (const float*)d_in[17];
    const float* bel = (const float*)d_in[18];
    float* out = (float*)d_out;

    __half *x16, *w016, *w116, *a016, *a116;
    float *sig0, *sig1, *b0, *b1, *wl, *bl;
    cudaGetSymbolAddress((void**)&x16,  g_x16);
    cudaGetSymbolAddress((void**)&w016, g_w016);
    cudaGetSymbolAddress((void**)&w116, g_w116);
    cudaGetSymbolAddress((void**)&a016, g_a016);
    cudaGetSymbolAddress((void**)&a116, g_a116);
    cudaGetSymbolAddress((void**)&sig0, g_sig0);
    cudaGetSymbolAddress((void**)&sig1, g_sig1);
    cudaGetSymbolAddress((void**)&b0,   g_b0);
    cudaGetSymbolAddress((void**)&b1,   g_b1);
    cudaGetSymbolAddress((void**)&wl,   g_wl);
    cudaGetSymbolAddress((void**)&bl,   g_bl);

    static bool attr_set = false;
    if (!attr_set) {
        cudaFuncSetAttribute(gemm_mma, cudaFuncAttributeMaxDynamicSharedMemorySize, SMEM_TOTAL);
        attr_set = true;
    }

    // sigmas (once per (k,n), NOT per sample)
    {
        int n = D_IN * D_H;
        prep_sig<<<(n + 255) / 256, 256>>>(wv0, sig0, n);
        n = D_H * D_H;
        prep_sig<<<(n + 255) / 256, 256>>>(wv1, sig1, n);
    }
    // x -> fp16 padded
    {
        int n = BATCH * K0PAD;
        prep_x<<<(n + 255) / 256, 256>>>(x, x16);
    }
    // bias 0, sampled W0
    {
        int total = S_SAMP * D_H;
        prep_sample<<<(total + 255) / 256, 256>>>(be0, bv0, bm0, b0, D_H, total);
        dim3 grid(K0PAD * D_H / (256 * 8), S_SAMP);
        prep_w<<<grid, 256>>>(we0, sig0, wm0, w016, D_IN, K0PAD);
    }
    // layer 0 GEMM
    {
        dim3 grid(D_H / GBN, BATCH / GBM, S_SAMP);
        gemm_mma<<<grid, 256, SMEM_TOTAL>>>(x16, 0, K0PAD, w016, b0, a016);
    }
    // sampled W1, bias 1
    {
        dim3 grid(D_H * D_H / (256 * 8), S_SAMP);
        prep_w<<<grid, 256>>>(we1, sig1, wm1, w116, D_H, D_H);
        int total = S_SAMP * D_H;
        prep_sample<<<(total + 255) / 256, 256>>>(be1, bv1, bm1, b1, D_H, total);
    }
    // layer 1 GEMM -> fp16 act1
    {
        dim3 grid(D_H / GBN, BATCH / GBM, S_SAMP);
        gemm_mma<<<grid, 256, SMEM_TOTAL>>>(a016, (size_t)BATCH * D_H, D_H, w116, b1, a116);
    }
    // last-layer sampling preps + final layer
    {
        int total = S_SAMP * D_H * D_OUT;
        prep_sample<<<(total + 255) / 256, 256>>>(wel, wlv, wlm, wl, D_H * D_OUT, total);
        total = S_SAMP * D_OUT;
        prep_sample<<<(total + 255) / 256, 256>>>(bel, blv, blm, bl, D_OUT, total);
    }
    {
        dim3 grid(BATCH / 128, S_SAMP);
        layer_out<<<grid, 256>>>(a116, wl, bl, out);
    }
}

// round 10
// speedup vs baseline: 2.2320x; 1.0012x over previous
#include <cuda_runtime.h>
#include <cuda_fp16.h>
#include <cstdint>
#include <math.h>

#define S_SAMP 32
#define BATCH  1024
#define D_IN   784
#define D_H    1024
#define D_OUT  10
#define K0PAD  832            // 784 padded to multiple of 64

// ---------------------------------------------------------------------------
// Device scratch (static: no cudaMalloc allowed)
// ---------------------------------------------------------------------------
__device__ __half g_x16[(size_t)BATCH * K0PAD];
__device__ __half g_w016[(size_t)S_SAMP * K0PAD * D_H];   // [S][Kpad][N] natural layout
__device__ __half g_w116[(size_t)S_SAMP * D_H * D_H];
__device__ __half g_a016[(size_t)S_SAMP * BATCH * D_H];
__device__ __half g_a116[(size_t)S_SAMP * BATCH * D_H];
__device__ float g_sig0[(size_t)D_IN * D_H];              // exp(0.5*wv0), shared across s
__device__ float g_sig1[(size_t)D_H * D_H];
__device__ float g_b0[S_SAMP * D_H];
__device__ float g_b1[S_SAMP * D_H];
__device__ float g_wl[S_SAMP * D_H * D_OUT];
__device__ float g_bl[S_SAMP * D_OUT];

// ---------------------------------------------------------------------------
// PTX helpers (arch-neutral only: cp.async, ldmatrix, mma.sync)
// ---------------------------------------------------------------------------
__device__ __forceinline__ uint32_t smem_u32(const void* p) {
    uint32_t a;
    asm("{ .reg .u64 t; cvta.to.shared.u64 t, %1; cvt.u32.u64 %0, t; }" : "=r"(a) : "l"(p));
    return a;
}
__device__ __forceinline__ void cp16(uint32_t dst, const void* src) {
    asm volatile("cp.async.cg.shared.global [%0], [%1], 16;" :: "r"(dst), "l"(src) : "memory");
}
#define CP_COMMIT() asm volatile("cp.async.commit_group;" ::: "memory")
#define CP_WAIT(n)  asm volatile("cp.async.wait_group %0;" :: "n"(n) : "memory")

__device__ __forceinline__ void ldsm4(uint32_t* r, uint32_t addr) {
    asm volatile("ldmatrix.sync.aligned.m8n8.x4.shared.b16 {%0,%1,%2,%3}, [%4];"
        : "=r"(r[0]), "=r"(r[1]), "=r"(r[2]), "=r"(r[3]) : "r"(addr));
}
__device__ __forceinline__ void ldsm4t(uint32_t* r, uint32_t addr) {
    asm volatile("ldmatrix.sync.aligned.m8n8.x4.trans.shared.b16 {%0,%1,%2,%3}, [%4];"
        : "=r"(r[0]), "=r"(r[1]), "=r"(r[2]), "=r"(r[3]) : "r"(addr));
}
__device__ __forceinline__ void mma_f16(float* d, const uint32_t* a, const uint32_t* b) {
    asm volatile("mma.sync.aligned.m16n8k16.row.col.f32.f16.f16.f32 "
        "{%0,%1,%2,%3}, {%4,%5,%6,%7}, {%8,%9}, {%0,%1,%2,%3};"
        : "+f"(d[0]), "+f"(d[1]), "+f"(d[2]), "+f"(d[3])
        : "r"(a[0]), "r"(a[1]), "r"(a[2]), "r"(a[3]), "r"(b[0]), "r"(b[1]));
}

// ---------------------------------------------------------------------------
// Prep kernels
// ---------------------------------------------------------------------------
__global__ void prep_sig(const float* __restrict__ wv, float* __restrict__ sig, int n) {
    int i = blockIdx.x * blockDim.x + threadIdx.x;
    if (i < n) sig[i] = expf(0.5f * wv[i]);
}

__global__ void prep_x(const float* __restrict__ x, __half* __restrict__ x16) {
    int i = blockIdx.x * blockDim.x + threadIdx.x;
    if (i >= BATCH * K0PAD) return;
    int b = i / K0PAD, k = i - b * K0PAD;
    float v = (k < D_IN) ? x[b * D_IN + k] : 0.0f;
    x16[i] = __float2half(v);
}

// Streaming sampled weights, [S][Kpad][N] natural layout, 8 elems/thread:
//   w16[s][k][n] = we[s][k][n] * sig[k][n] + wm[k][n]   (k >= K -> 0)
__global__ void __launch_bounds__(256) prep_w(
    const float* __restrict__ we, const float* __restrict__ sig,
    const float* __restrict__ wm, __half* __restrict__ w16,
    int K, int Kpad)
{
    const int s = blockIdx.y;
    const int i = (blockIdx.x * 256 + threadIdx.x) * 8;   // element index in plane
    if (i >= Kpad * D_H) return;
    const int k = i >> 10;
    const int n = i & 1023;

    uint4 outv;
    if (k < K) {
        const float* weP = we + ((size_t)s * K + k) * D_H + n;
        const float* sgP = sig + k * D_H + n;
        const float* wmP = wm  + k * D_H + n;
        float4 e0 = *(const float4*)(weP);
        float4 e1 = *(const float4*)(weP + 4);
        float4 s0 = *(const float4*)(sgP);
        float4 s1 = *(const float4*)(sgP + 4);
        float4 m0 = *(const float4*)(wmP);
        float4 m1 = *(const float4*)(wmP + 4);
        __half2 h0 = __floats2half2_rn(fmaf(e0.x, s0.x, m0.x), fmaf(e0.y, s0.y, m0.y));
        __half2 h1 = __floats2half2_rn(fmaf(e0.z, s0.z, m0.z), fmaf(e0.w, s0.w, m0.w));
        __half2 h2 = __floats2half2_rn(fmaf(e1.x, s1.x, m1.x), fmaf(e1.y, s1.y, m1.y));
        __half2 h3 = __floats2half2_rn(fmaf(e1.z, s1.z, m1.z), fmaf(e1.w, s1.w, m1.w));
        outv = make_uint4(*(uint32_t*)&h0, *(uint32_t*)&h1, *(uint32_t*)&h2, *(uint32_t*)&h3);
    } else {
        outv = make_uint4(0, 0, 0, 0);
    }
    *(uint4*)(w16 + (size_t)s * Kpad * D_H + i) = outv;
}

__global__ void prep_sample(const float* __restrict__ e, const float* __restrict__ v,
                            const float* __restrict__ m, float* __restrict__ out,
                            int n, int total) {
    int i = blockIdx.x * blockDim.x + threadIdx.x;
    if (i < total) {
        int j = i % n;
        out[i] = fmaf(e[i], expf(0.5f * v[j]), m[j]);
    }
}

// ---------------------------------------------------------------------------
// HMMA GEMM, fp16 single term, 3-stage cp.async pipeline:
//   C[s] = relu(A16[s] @ W16[s] + bias[s]) -> fp16
// ---------------------------------------------------------------------------
#define GBM 128
#define GBN 128
#define GBK 64
#define NSTAGE 3
#define ROWB_A 144                   // A smem row stride: 128B data + 16 pad
#define A_MATB (128 * ROWB_A)        // 18432 B
#define ROWB_W 272                   // W smem k-row stride: 256B data + 16 pad
#define W_MATB (64 * ROWB_W)         // 17408 B
#define STAGEB (A_MATB + W_MATB)     // 35840 B
#define SMEM_TOTAL (NSTAGE * STAGEB) // 107520 B

__global__ void __launch_bounds__(256, 2) gemm_mma(
    const __half* __restrict__ A16, size_t aStrideS, int Kpad,
    const __half* __restrict__ W16,
    const float* __restrict__ bias,
    __half* __restrict__ Ch)
{
    extern __shared__ __align__(16) char dynsmem[];
    const uint32_t sbase = smem_u32(dynsmem);

    const int tid  = threadIdx.x;
    const int wid  = tid >> 5;
    const int lane = tid & 31;
    const int s  = blockIdx.z;
    const int m0 = blockIdx.y * GBM;
    const int n0 = blockIdx.x * GBN;

    const int warp_m = wid >> 1;
    const int warp_n = wid & 1;

    const __half* aG = A16 + (size_t)s * aStrideS + (size_t)m0 * Kpad;
    const __half* wG = W16 + (size_t)s * Kpad * D_H + n0;

    const int firstHalf = (tid < 128);
    const int lrowA = tid & 127;
    const int wj    = tid & 127;
    const int wrow  = wj >> 1;
    const int wgrp  = wj & 1;

    auto load_chunk = [&](uint32_t st, int k0) {
        if (firstHalf) {
#pragma unroll
            for (int c = 0; c < 8; c++)
                cp16(st + (uint32_t)lrowA * ROWB_A + c * 16,
                     aG + (size_t)lrowA * Kpad + k0 + c * 8);
        } else {
#pragma unroll
            for (int c = 0; c < 8; c++)
                cp16(st + A_MATB + (uint32_t)wrow * ROWB_W + wgrp * 128 + c * 16,
                     wG + (size_t)(k0 + wrow) * D_H + wgrp * 64 + c * 8);
        }
        CP_COMMIT();
    };

    const uint32_t aLaneOff = (uint32_t)(lane & 15) * ROWB_A + (uint32_t)(lane >> 4) * 16
                            + (uint32_t)(warp_m * 32) * ROWB_A;
    const int bm = lane >> 3, br = lane & 7;
    const uint32_t bTransOff = (uint32_t)((bm & 1) * 8 + br) * ROWB_W + (uint32_t)(bm >> 1) * 16
                             + (uint32_t)warp_n * 128;

    float acc[2][8][4];
#pragma unroll
    for (int i = 0; i < 2; i++)
#pragma unroll
        for (int j = 0; j < 8; j++)
#pragma unroll
            for (int q = 0; q < 4; q++) acc[i][j][q] = 0.0f;

    const int nchunks = Kpad / GBK;

    load_chunk(sbase, 0);
    if (nchunks > 1) load_chunk(sbase + STAGEB, GBK);

    int stage = 0;
    for (int it = 0; it < nchunks; it++) {
        if (it + 2 < nchunks) {
            int pst = stage + 2; if (pst >= NSTAGE) pst -= NSTAGE;
            load_chunk(sbase + (uint32_t)pst * STAGEB, (it + 2) * GBK);
            CP_WAIT(2);
        } else if (it + 1 < nchunks) {
            CP_WAIT(1);
        } else {
            CP_WAIT(0);
        }
        __syncthreads();

        const uint32_t st = sbase + (uint32_t)stage * STAGEB;
        const uint32_t aS = st + aLaneOff;
        const uint32_t bS = st + A_MATB + bTransOff;

#pragma unroll
        for (int ks = 0; ks < 4; ks++) {
            uint32_t aa[2][4], bb[16];
#pragma unroll
            for (int mi = 0; mi < 2; mi++)
                ldsm4(aa[mi], aS + mi * 16 * ROWB_A + ks * 32);
#pragma unroll
            for (int p = 0; p < 4; p++)
                ldsm4t(&bb[p * 4], bS + ks * 16 * ROWB_W + p * 32);
#pragma unroll
            for (int mi = 0; mi < 2; mi++)
#pragma unroll
                for (int nj = 0; nj < 8; nj++)
                    mma_f16(acc[mi][nj], aa[mi], &bb[nj * 2]);
        }
        __syncthreads();
        if (++stage >= NSTAGE) stage = 0;
    }

    // ---- epilogue: bias + relu -> fp16 ----
    const int colBase = n0 + warp_n * 64 + (lane & 3) * 2;
    const int rowBase = m0 + warp_m * 32 + (lane >> 2);
    float bias2[8][2];
#pragma unroll
    for (int nj = 0; nj < 8; nj++) {
        const float* bp = bias + (size_t)s * D_H + colBase + nj * 8;
        bias2[nj][0] = bp[0];
        bias2[nj][1] = bp[1];
    }

#pragma unroll
    for (int mi = 0; mi < 2; mi++) {
#pragma unroll
        for (int h = 0; h < 2; h++) {
            const int row = rowBase + mi * 16 + h * 8;
            const size_t rowOff = ((size_t)s * BATCH + row) * D_H;
#pragma unroll
            for (int nj = 0; nj < 8; nj++) {
                float v0 = fmaxf(acc[mi][nj][2 * h]     + bias2[nj][0], 0.0f);
                float v1 = fmaxf(acc[mi][nj][2 * h + 1] + bias2[nj][1], 0.0f);
                __half2 hv = __floats2half2_rn(v0, v1);
                *(__half2*)(Ch + rowOff + colBase + nj * 8) = hv;
            }
        }
    }
}

// ---------------------------------------------------------------------------
// Last layer: out[s,b,o] = act16[s,b,:] . wl[s,:,o] + bl[s,o]
// ---------------------------------------------------------------------------
__global__ void __launch_bounds__(256) layer_out(
    const __half* __restrict__ act, const float* __restrict__ wls,
    const float* __restrict__ bls, float* __restrict__ out)
{
    const int s  = blockIdx.y;
    const int m0 = blockIdx.x * 128;

    __shared__ float As[128][33];
    __shared__ float ws[32 * D_OUT];

    const int tid   = threadIdx.x;
    const int crow  = tid >> 1;
    const int obase = (tid & 1) * 5;

    float acc[5] = {0.f, 0.f, 0.f, 0.f, 0.f};
    const int lr = tid >> 2;             // 0..63
    const int lk = (tid & 3) * 8;        // 0,8,16,24

    for (int kt = 0; kt < D_H; kt += 32) {
#pragma unroll
        for (int rr = 0; rr < 2; rr++) {
            int r = lr + rr * 64;
            uint4 v = *(const uint4*)(act + ((size_t)s * BATCH + m0 + r) * D_H + kt + lk);
            const __half2* hp = (const __half2*)&v;
#pragma unroll
            for (int q = 0; q < 4; q++) {
                float2 f = __half22float2(hp[q]);
                As[r][lk + 2 * q]     = f.x;
                As[r][lk + 2 * q + 1] = f.y;
            }
        }
        for (int i = tid; i < 32 * D_OUT; i += 256)
            ws[i] = wls[(size_t)s * D_H * D_OUT + kt * D_OUT + i];
        __syncthreads();
#pragma unroll
        for (int k = 0; k < 32; k++) {
            float a = As[crow][k];
#pragma unroll
            for (int j = 0; j < 5; j++)
                acc[j] = fmaf(a, ws[k * D_OUT + obase + j], acc[j]);
        }
        __syncthreads();
    }
#pragma unroll
    for (int j = 0; j < 5; j++)
        out[((size_t)s * BATCH + m0 + crow) * D_OUT + obase + j] = acc[j] + bls[s * D_OUT + obase + j];
}

// ---------------------------------------------------------------------------
// kernel_launch — two-stream fork so layer-1/last-layer preps overlap GEMM0.
//   stream0: sig0, x, b0, w0, GEMM0 .......... join .. GEMM1, layer_out
//   strm2:   (fork) sig1, w1, b1, wl, bl ....../
// ---------------------------------------------------------------------------
extern "C" void kernel_launch(void* const* d_in, const int* in_sizes, int n_in,
                              void* d_out, int out_size) {
    const float* x   = (const float*)d_in[0];
    const float* wm0 = (const float*)d_in[1];
    const float* wv0 = (const float*)d_in[2];
    const float* bm0 = (const float*)d_in[3];
    const float* bv0 = (const float*)d_in[4];
    const float* wm1 = (const float*)d_in[5];
    const float* wv1 = (const float*)d_in[6];
    const float* bm1 = (const float*)d_in[7];
    const float* bv1 = (const float*)d_in[8];
    const float* wlm = (const float*)d_in[9];
    const float* wlv = (const float*)d_in[10];
    const float* blm = (const float*)d_in[11];
    const float* blv = (const float*)d_in[12];
    const float* we0 = (const float*)d_in[13];
    const float* be0 = (const float*)d_in[14];
    const float* we1 = (const float*)d_in[15];
    const float* be1 = (const float*)d_in[16];
    const float* wel = (const float*)d_in[17];
    const float* bel = (const float*)d_in[18];
    float* out = (float*)d_out;

    __half *x16, *w016, *w116, *a016, *a116;
    float *sig0, *sig1, *b0, *b1, *wl, *bl;
    cudaGetSymbolAddress((void**)&x16,  g_x16);
    cudaGetSymbolAddress((void**)&w016, g_w016);
    cudaGetSymbolAddress((void**)&w116, g_w116);
    cudaGetSymbolAddress((void**)&a016, g_a016);
    cudaGetSymbolAddress((void**)&a116, g_a116);
    cudaGetSymbolAddress((void**)&sig0, g_sig0);
    cudaGetSymbolAddress((void**)&sig1, g_sig1);
    cudaGetSymbolAddress((void**)&b0,   g_b0);
    cudaGetSymbolAddress((void**)&b1,   g_b1);
    cudaGetSymbolAddress((void**)&wl,   g_wl);
    cudaGetSymbolAddress((void**)&bl,   g_bl);

    static bool init_done = false;
    static cudaStream_t strm2 = nullptr;
    static cudaEvent_t evFork = nullptr, evJoin = nullptr;
    if (!init_done) {
        cudaFuncSetAttribute(gemm_mma, cudaFuncAttributeMaxDynamicSharedMemorySize, SMEM_TOTAL);
        cudaStreamCreateWithFlags(&strm2, cudaStreamNonBlocking);
        cudaEventCreateWithFlags(&evFork, cudaEventDisableTiming);
        cudaEventCreateWithFlags(&evJoin, cudaEventDisableTiming);
        init_done = true;
    }

    // ---- fork ----
    cudaEventRecord(evFork, 0);
    cudaStreamWaitEvent(strm2, evFork, 0);

    // ---- side stream: everything GEMM0 does NOT need ----
    {
        int n = D_H * D_H;
        prep_sig<<<(n + 255) / 256, 256, 0, strm2>>>(wv1, sig1, n);
        dim3 grid(D_H * D_H / (256 * 8), S_SAMP);
        prep_w<<<grid, 256, 0, strm2>>>(we1, sig1, wm1, w116, D_H, D_H);
        int total = S_SAMP * D_H;
        prep_sample<<<(total + 255) / 256, 256, 0, strm2>>>(be1, bv1, bm1, b1, D_H, total);
        total = S_SAMP * D_H * D_OUT;
        prep_sample<<<(total + 255) / 256, 256, 0, strm2>>>(wel, wlv, wlm, wl, D_H * D_OUT, total);
        total = S_SAMP * D_OUT;
        prep_sample<<<(total + 255) / 256, 256, 0, strm2>>>(bel, blv, blm, bl, D_OUT, total);
        cudaEventRecord(evJoin, strm2);
    }

    // ---- main stream: GEMM0 critical path ----
    {
        int n = D_IN * D_H;
        prep_sig<<<(n + 255) / 256, 256>>>(wv0, sig0, n);
        n = BATCH * K0PAD;
        prep_x<<<(n + 255) / 256, 256>>>(x, x16);
        int total = S_SAMP * D_H;
        prep_sample<<<(total + 255) / 256, 256>>>(be0, bv0, bm0, b0, D_H, total);
        dim3 gw(K0PAD * D_H / (256 * 8), S_SAMP);
        prep_w<<<gw, 256>>>(we0, sig0, wm0, w016, D_IN, K0PAD);
        dim3 grid(D_H / GBN, BATCH / GBM, S_SAMP);
        gemm_mma<<<grid, 256, SMEM_TOTAL>>>(x16, 0, K0PAD, w016, b0, a016);
    }

    // ---- join, then layer 1 + output ----
    cudaStreamWaitEvent(0, evJoin, 0);
    {
        dim3 grid(D_H / GBN, BATCH / GBM, S_SAMP);
        gemm_mma<<<grid, 256, SMEM_TOTAL>>>(a016, (size_t)BATCH * D_H, D_H, w116, b1, a116);
    }
    {
        dim3 grid(BATCH / 128, S_SAMP);
        layer_out<<<grid, 256>>>(a116, wl, bl, out);
    }
}